// round 12
// baseline (speedup 1.0000x reference)
#include <cuda_runtime.h>
#include <cuda_bf16.h>
#include <math.h>
#include <stdint.h>

// ---------------- Model constants ----------------
#define LNUM 8
#define H    1024
#define NH   16
#define NKV  8
#define HD   128
#define IDIM 3072
#define VOC  32000
#define BATCH 2
#define SEQ  1024
#define TOK  (BATCH*SEQ)          // 2048
#define QD   (NH*HD)              // 2048
#define KVD  (NKV*HD)             // 1024
#define EPS  1e-6f
#define ATT_SCALE 0.08838834764831845f

// Per-layer weight scratch offsets (bf16 hi/lo, [N][K] layout, reused each layer)
#define WQK 0                              // [3072][1024]  (Q rows 0-2047, K rows 2048-3071)
#define WV  (3072*1024)                    // [1024][1024]
#define WO  (WV + 1024*1024)               // [1024][2048]
#define WGU (WO + 1024*2048)               // [6144][1024]  (G rows 0-3071, U rows 3072-6143)
#define WD  (WGU + 6144*1024)              // [1024][3072]
#define WBUF ((size_t)VOC * H)             // 32,768,000 (also fits LM head)

// ---------------- Scratch (device globals; no allocation allowed) ----------------
__device__ float g_h  [(size_t)TOK * H];
__device__ float g_qk [(size_t)TOK * 3072];
__device__ float g_gu [(size_t)TOK * 6144];
__device__ float g_cos[(size_t)SEQ * 64];
__device__ float g_sin[(size_t)SEQ * 64];
__device__ __nv_bfloat16 g_wT_hi[WBUF];
__device__ __nv_bfloat16 g_wT_lo[WBUF];
__device__ __nv_bfloat16 g_a_hi[(size_t)TOK * IDIM];
__device__ __nv_bfloat16 g_a_lo[(size_t)TOK * IDIM];
__device__ __nv_bfloat16 g_qh[(size_t)TOK * QD];
__device__ __nv_bfloat16 g_ql[(size_t)TOK * QD];
__device__ __nv_bfloat16 g_kh[(size_t)TOK * KVD];
__device__ __nv_bfloat16 g_kl[(size_t)TOK * KVD];
__device__ __nv_bfloat16 g_vth[(size_t)TOK * KVD];   // [b][kvh][dim][seq]
__device__ __nv_bfloat16 g_vtl[(size_t)TOK * KVD];

// ---------------- PTX helpers ----------------
__device__ __forceinline__ uint32_t smem_to_u32(const void* p) {
    uint32_t a;
    asm("{ .reg .u64 t; cvta.to.shared.u64 t, %1; cvt.u32.u64 %0, t; }" : "=r"(a) : "l"(p));
    return a;
}
__device__ __forceinline__ void cp16(uint32_t s, const void* g) {
    asm volatile("cp.async.cg.shared.global [%0], [%1], 16;" :: "r"(s), "l"(g));
}
__device__ __forceinline__ void ldsm4(uint32_t* r, uint32_t addr) {
    asm volatile("ldmatrix.sync.aligned.m8n8.x4.shared.b16 {%0,%1,%2,%3}, [%4];"
                 : "=r"(r[0]), "=r"(r[1]), "=r"(r[2]), "=r"(r[3]) : "r"(addr));
}
__device__ __forceinline__ void mma_bf16(float* c, const uint32_t* a, uint32_t b0, uint32_t b1) {
    asm volatile("mma.sync.aligned.m16n8k16.row.col.f32.bf16.bf16.f32 "
                 "{%0,%1,%2,%3}, {%4,%5,%6,%7}, {%8,%9}, {%0,%1,%2,%3};"
                 : "+f"(c[0]), "+f"(c[1]), "+f"(c[2]), "+f"(c[3])
                 : "r"(a[0]), "r"(a[1]), "r"(a[2]), "r"(a[3]), "r"(b0), "r"(b1));
}
#define SWZ(off) ((off) ^ (((off) >> 3) & 0x70))

__device__ __forceinline__ uint32_t pack_bf16(float a, float b) {
    __nv_bfloat162 h;
    h.x = __float2bfloat16(a);
    h.y = __float2bfloat16(b);
    return *(uint32_t*)&h;
}

// ---------------- Concat weight transpose + hi/lo bf16 split -------------------------
// Wa [K x Na], Wb [K x Nb] fp32 -> T [(Na+Nb)][K] bf16 hi/lo (Wa rows first).
__global__ __launch_bounds__(256) void convT2_kernel(
    const float* __restrict__ Wa, const float* __restrict__ Wb,
    __nv_bfloat16* __restrict__ Th, __nv_bfloat16* __restrict__ Tl,
    int K, int Na, int Nb) {
    __shared__ float sm[64][65];
    int n0 = blockIdx.x * 64, k0 = blockIdx.y * 64;
    const float* W; int col0, Nsrc;
    if (n0 < Na) { W = Wa; col0 = n0; Nsrc = Na; }
    else         { W = Wb; col0 = n0 - Na; Nsrc = Nb; }
    int t = threadIdx.x;
    int rr = t >> 4, cc = (t & 15) * 4;
#pragma unroll
    for (int it = 0; it < 4; it++) {
        int kr = rr + it * 16;
        float4 v = *(const float4*)&W[(size_t)(k0 + kr) * Nsrc + col0 + cc];
        sm[kr][cc + 0] = v.x;  sm[kr][cc + 1] = v.y;
        sm[kr][cc + 2] = v.z;  sm[kr][cc + 3] = v.w;
    }
    __syncthreads();
#pragma unroll
    for (int it = 0; it < 4; it++) {
        int nr = rr + it * 16;
        float v0 = sm[cc + 0][nr], v1 = sm[cc + 1][nr];
        float v2 = sm[cc + 2][nr], v3 = sm[cc + 3][nr];
        __nv_bfloat16 h0 = __float2bfloat16(v0), h1 = __float2bfloat16(v1);
        __nv_bfloat16 h2 = __float2bfloat16(v2), h3 = __float2bfloat16(v3);
        uint32_t hp0 = pack_bf16(v0, v1), hp1 = pack_bf16(v2, v3);
        uint32_t lp0 = pack_bf16(v0 - __bfloat162float(h0), v1 - __bfloat162float(h1));
        uint32_t lp1 = pack_bf16(v2 - __bfloat162float(h2), v3 - __bfloat162float(h3));
        size_t o = (size_t)(n0 + nr) * K + k0 + cc;
        *(uint2*)&Th[o] = make_uint2(hp0, hp1);
        *(uint2*)&Tl[o] = make_uint2(lp0, lp1);
    }
}

// ---------------- bf16x3 GEMM via mma.sync: C = A @ B^T (B stored [N][K]) -----------
// 128x128 CTA tile, 8 warps (2x4), warp 64x32, BK=64, 3-stage cp.async, 1 barrier/iter.
// mode 0: C = result; mode 1: C += result; mode 2: write V-transposed bf16 hi/lo.
#define STG 65536
#define GSM_TOTAL (3 * STG)
__global__ __launch_bounds__(256) void gemm_mma_kernel(
    const __nv_bfloat16* __restrict__ Ah, const __nv_bfloat16* __restrict__ Al,
    const __nv_bfloat16* __restrict__ Bh, const __nv_bfloat16* __restrict__ Bl,
    float* __restrict__ C, __nv_bfloat16* __restrict__ Oh, __nv_bfloat16* __restrict__ Ol,
    int M, int N, int K, int mode) {
    extern __shared__ char smem[];
    uint32_t sb = smem_to_u32(smem);
    int tid = threadIdx.x, lane = tid & 31, wid = tid >> 5;
    int brow = blockIdx.y * 128, bcol = blockIdx.x * 128;
    int wm = wid & 1, wn = wid >> 1;

    float acc[4][4][4] = {};
    int T = K >> 6;

    auto issue_loads = [&](int t) {
        uint32_t st = sb + (uint32_t)(t % 3) * STG;
        int k0 = t << 6;
#pragma unroll
        for (int i = 0; i < 4; i++) {
            int idx = tid + i * 256;
            int r = idx >> 3, g = idx & 7;
            uint32_t off = SWZ((uint32_t)(r * 128 + g * 16));
            size_t ga = (size_t)(brow + r) * K + k0 + g * 8;
            size_t gb = (size_t)(bcol + r) * K + k0 + g * 8;
            cp16(st + off,         Ah + ga);
            cp16(st + 16384 + off, Al + ga);
            cp16(st + 32768 + off, Bh + gb);
            cp16(st + 49152 + off, Bl + gb);
        }
        asm volatile("cp.async.commit_group;");
    };

    issue_loads(0);
    issue_loads(1);

    uint32_t a_roff = (uint32_t)(wm * 64 + (lane & 15));
    uint32_t a_koff = (uint32_t)((lane >> 4) * 8);
    uint32_t b_noff = (uint32_t)(wn * 32 + ((lane >> 4) * 8) + (lane & 7));
    uint32_t b_koff = (uint32_t)(((lane >> 3) & 1) * 8);

    for (int t = 0; t < T; t++) {
        if (t == T - 1) asm volatile("cp.async.wait_group 0;");
        else            asm volatile("cp.async.wait_group 1;");
        __syncthreads();
        if (t + 2 < T) issue_loads(t + 2);
        uint32_t st = sb + (uint32_t)(t % 3) * STG;
#pragma unroll
        for (int kk = 0; kk < 4; kk++) {
            uint32_t ah_[4][4], al_[4][4];
#pragma unroll
            for (int mi = 0; mi < 4; mi++) {
                uint32_t off = SWZ((a_roff + mi * 16) * 128 + (kk * 16 + a_koff) * 2);
                ldsm4(ah_[mi], st + off);
                ldsm4(al_[mi], st + 16384 + off);
            }
            uint32_t bh_[2][4], bl_[2][4];
#pragma unroll
            for (int p = 0; p < 2; p++) {
                uint32_t off = SWZ((b_noff + p * 16) * 128 + (kk * 16 + b_koff) * 2);
                ldsm4(bh_[p], st + 32768 + off);
                ldsm4(bl_[p], st + 49152 + off);
            }
#pragma unroll
            for (int mi = 0; mi < 4; mi++)
#pragma unroll
                for (int ni = 0; ni < 4; ni++) {
                    int p = ni >> 1, q2 = (ni & 1) * 2;
                    mma_bf16(acc[mi][ni], ah_[mi], bh_[p][q2], bh_[p][q2 + 1]);
                    mma_bf16(acc[mi][ni], ah_[mi], bl_[p][q2], bl_[p][q2 + 1]);
                    mma_bf16(acc[mi][ni], al_[mi], bh_[p][q2], bh_[p][q2 + 1]);
                }
        }
    }

#pragma unroll
    for (int mi = 0; mi < 4; mi++)
#pragma unroll
        for (int ni = 0; ni < 4; ni++) {
            int r0 = brow + wm * 64 + mi * 16 + (lane >> 2);
            int c0 = bcol + wn * 32 + ni * 8 + 2 * (lane & 3);
            float* a4 = acc[mi][ni];
            if (mode == 2) {
#pragma unroll
                for (int e = 0; e < 4; e++) {
                    int r = r0 + (e >> 1) * 8;
                    int c = c0 + (e & 1);
                    int b = r >> 10, seq = r & 1023;
                    int kvh = c >> 7, hd = c & 127;
                    size_t idx = ((size_t)((b * NKV + kvh) * HD + hd)) * SEQ + seq;
                    float v = a4[e];
                    __nv_bfloat16 hi = __float2bfloat16(v);
                    Oh[idx] = hi;
                    Ol[idx] = __float2bfloat16(v - __bfloat162float(hi));
                }
            } else {
                float2* p0 = (float2*)(C + (size_t)r0 * N + c0);
                float2* p1 = (float2*)(C + (size_t)(r0 + 8) * N + c0);
                if (mode == 1) {
                    float2 v0 = *p0, v1 = *p1;
                    v0.x += a4[0]; v0.y += a4[1];
                    v1.x += a4[2]; v1.y += a4[3];
                    *p0 = v0; *p1 = v1;
                } else {
                    *p0 = make_float2(a4[0], a4[1]);
                    *p1 = make_float2(a4[2], a4[3]);
                }
            }
        }
}

// ---------------- Tensor-core flash attention: 128-query blocks, double-buffered -----
// smem: QH 0..32K | QL 32K..64K | stages s=0,1 at 64K + s*64K:
//   KH +0 (2 chunks x 8K), KL +16K, VH +32K, VL +48K
#define ASM_BYTES 196608
__global__ __launch_bounds__(256, 1) void flash_attn_tc_kernel(
    const __nv_bfloat16* __restrict__ qh, const __nv_bfloat16* __restrict__ ql,
    const __nv_bfloat16* __restrict__ kh, const __nv_bfloat16* __restrict__ kl,
    const __nv_bfloat16* __restrict__ vth, const __nv_bfloat16* __restrict__ vtl,
    __nv_bfloat16* __restrict__ oh, __nv_bfloat16* __restrict__ ol) {
    extern __shared__ char smem[];
    uint32_t sb = smem_to_u32(smem);
    int tid = threadIdx.x, lane = tid & 31, w = tid >> 5;
    int gid = blockIdx.x;
    int qt = 7 - (gid & 7);            // heavy tiles first
    int hh = (gid >> 3) & 15;
    int b  = gid >> 7;
    int t0 = qt * 128;
    int kvh = hh >> 1;

    // ---- Q load (hi/lo, 2 dim-chunks of 64) ----
    for (int i = tid; i < 2048; i += 256) {
        int c = i >> 10, r = (i >> 3) & 127, g = i & 7;
        uint32_t off = (uint32_t)c * 16384u + SWZ((uint32_t)(r * 128 + g * 16));
        size_t gq = ((size_t)(b * SEQ + t0 + r) * NH + hh) * HD + c * 64 + g * 8;
        cp16(sb + off,          qh + gq);
        cp16(sb + 32768 + off,  ql + gq);
    }
    asm volatile("cp.async.commit_group;");

    int T = (t0 >> 6) + 2;

    auto issue_kv = [&](int i) {
        uint32_t st = sb + 65536u + (uint32_t)(i & 1) * 65536u;
        int j0 = i << 6;
        for (int x = tid; x < 2048; x += 256) {
            if (x < 1024) {
                int c = x >> 9, r = (x >> 3) & 63, g = x & 7;
                uint32_t off = (uint32_t)c * 8192u + SWZ((uint32_t)(r * 128 + g * 16));
                size_t gk = ((size_t)(b * SEQ + j0 + r) * NKV + kvh) * HD + c * 64 + g * 8;
                cp16(st + off,         kh + gk);
                cp16(st + 16384 + off, kl + gk);
            } else {
                int y = x - 1024;
                int dim = y >> 3, g = y & 7;
                uint32_t off = SWZ((uint32_t)(dim * 128 + g * 16));
                size_t gv = ((size_t)((b * NKV + kvh) * HD + dim)) * SEQ + j0 + g * 8;
                cp16(st + 32768 + off, vth + gv);
                cp16(st + 49152 + off, vtl + gv);
            }
        }
        asm volatile("cp.async.commit_group;");
    };

    issue_kv(0);
    asm volatile("cp.async.wait_group 1;");   // Q complete (stage0 may be pending)
    __syncthreads();

    // ---- extract Q fragments ----
    uint32_t qah[2][4][4], qal[2][4][4];
#pragma unroll
    for (int c = 0; c < 2; c++)
#pragma unroll
        for (int kk = 0; kk < 4; kk++) {
            uint32_t off = (uint32_t)c * 16384u +
                SWZ((uint32_t)((w * 16 + (lane & 15)) * 128 + (kk * 16 + (lane >> 4) * 8) * 2));
            ldsm4(qah[c][kk], sb + off);
            ldsm4(qal[c][kk], sb + 32768 + off);
        }

    float cacc[16][4] = {};
    float m0 = -1e30f, m1 = -1e30f, l0 = 0.f, l1 = 0.f;
    int r0g = t0 + w * 16 + (lane >> 2);
    int r1g = r0g + 8;
    int wmax = t0 + w * 16 + 15;

    for (int i = 0; i < T; i++) {
        asm volatile("cp.async.wait_group 0;");
        __syncthreads();
        if (i + 1 < T) issue_kv(i + 1);
        int j0 = i << 6;
        if (j0 <= wmax) {
            uint32_t stK = sb + 65536u + (uint32_t)(i & 1) * 65536u;
            uint32_t stV = stK + 32768u;

            // ---- S = Q K^T (bf16x3) ----
            float sacc[8][4] = {};
#pragma unroll
            for (int c = 0; c < 2; c++)
#pragma unroll
                for (int kk = 0; kk < 4; kk++) {
#pragma unroll
                    for (int p = 0; p < 4; p++) {
                        uint32_t off = (uint32_t)c * 8192u +
                            SWZ((uint32_t)((p * 16 + (lane >> 4) * 8 + (lane & 7)) * 128 +
                                           (kk * 16 + ((lane >> 3) & 1) * 8) * 2));
                        uint32_t bh4[4], bl4[4];
                        ldsm4(bh4, stK + off);
                        ldsm4(bl4, stK + 16384 + off);
                        mma_bf16(sacc[2 * p],     qah[c][kk], bh4[0], bh4[1]);
                        mma_bf16(sacc[2 * p],     qah[c][kk], bl4[0], bl4[1]);
                        mma_bf16(sacc[2 * p],     qal[c][kk], bh4[0], bh4[1]);
                        mma_bf16(sacc[2 * p + 1], qah[c][kk], bh4[2], bh4[3]);
                        mma_bf16(sacc[2 * p + 1], qah[c][kk], bl4[2], bl4[3]);
                        mma_bf16(sacc[2 * p + 1], qal[c][kk], bh4[2], bh4[3]);
                    }
                }

            // ---- causal mask (tiles straddling the diagonal) ----
            if (j0 + 63 > r0g) {
#pragma unroll
                for (int ni = 0; ni < 8; ni++) {
                    int colb = j0 + ni * 8 + 2 * (lane & 3);
                    if (colb     > r0g) sacc[ni][0] = -1e30f;
                    if (colb + 1 > r0g) sacc[ni][1] = -1e30f;
                    if (colb     > r1g) sacc[ni][2] = -1e30f;
                    if (colb + 1 > r1g) sacc[ni][3] = -1e30f;
                }
            }

            // ---- online softmax ----
            float rmax0 = -1e30f, rmax1 = -1e30f;
#pragma unroll
            for (int ni = 0; ni < 8; ni++) {
                rmax0 = fmaxf(rmax0, fmaxf(sacc[ni][0], sacc[ni][1]));
                rmax1 = fmaxf(rmax1, fmaxf(sacc[ni][2], sacc[ni][3]));
            }
            rmax0 = fmaxf(rmax0, __shfl_xor_sync(0xffffffffu, rmax0, 1));
            rmax0 = fmaxf(rmax0, __shfl_xor_sync(0xffffffffu, rmax0, 2));
            rmax1 = fmaxf(rmax1, __shfl_xor_sync(0xffffffffu, rmax1, 1));
            rmax1 = fmaxf(rmax1, __shfl_xor_sync(0xffffffffu, rmax1, 2));
            float mn0 = fmaxf(m0, rmax0), mn1 = fmaxf(m1, rmax1);
            float corr0 = __expf(m0 - mn0), corr1 = __expf(m1 - mn1);
            float rs0 = 0.f, rs1 = 0.f;
#pragma unroll
            for (int ni = 0; ni < 8; ni++) {
                sacc[ni][0] = __expf(sacc[ni][0] - mn0);
                sacc[ni][1] = __expf(sacc[ni][1] - mn0);
                sacc[ni][2] = __expf(sacc[ni][2] - mn1);
                sacc[ni][3] = __expf(sacc[ni][3] - mn1);
                rs0 += sacc[ni][0] + sacc[ni][1];
                rs1 += sacc[ni][2] + sacc[ni][3];
            }
            rs0 += __shfl_xor_sync(0xffffffffu, rs0, 1);
            rs0 += __shfl_xor_sync(0xffffffffu, rs0, 2);
            rs1 += __shfl_xor_sync(0xffffffffu, rs1, 1);
            rs1 += __shfl_xor_sync(0xffffffffu, rs1, 2);
            l0 = l0 * corr0 + rs0;  m0 = mn0;
            l1 = l1 * corr1 + rs1;  m1 = mn1;
#pragma unroll
            for (int n = 0; n < 16; n++) {
                cacc[n][0] *= corr0; cacc[n][1] *= corr0;
                cacc[n][2] *= corr1; cacc[n][3] *= corr1;
            }

            // ---- ctx += P V (bf16x3) ----
#pragma unroll
            for (int kk = 0; kk < 4; kk++) {
                uint32_t pah[4], pal[4];
                float* s0 = sacc[2 * kk];
                float* s1 = sacc[2 * kk + 1];
                pah[0] = pack_bf16(s0[0], s0[1]);
                pah[1] = pack_bf16(s0[2], s0[3]);
                pah[2] = pack_bf16(s1[0], s1[1]);
                pah[3] = pack_bf16(s1[2], s1[3]);
                {
                    __nv_bfloat162* hx;
                    hx = (__nv_bfloat162*)&pah[0];
                    pal[0] = pack_bf16(s0[0] - __bfloat162float(hx->x), s0[1] - __bfloat162float(hx->y));
                    hx = (__nv_bfloat162*)&pah[1];
                    pal[1] = pack_bf16(s0[2] - __bfloat162float(hx->x), s0[3] - __bfloat162float(hx->y));
                    hx = (__nv_bfloat162*)&pah[2];
                    pal[2] = pack_bf16(s1[0] - __bfloat162float(hx->x), s1[1] - __bfloat162float(hx->y));
                    hx = (__nv_bfloat162*)&pah[3];
                    pal[3] = pack_bf16(s1[2] - __bfloat162float(hx->x), s1[3] - __bfloat162float(hx->y));
                }
#pragma unroll
                for (int p = 0; p < 8; p++) {
                    uint32_t off = SWZ((uint32_t)((p * 16 + (lane >> 4) * 8 + (lane & 7)) * 128 +
                                                  (kk * 16 + ((lane >> 3) & 1) * 8) * 2));
                    uint32_t vh4[4], vl4[4];
                    ldsm4(vh4, stV + off);
                    ldsm4(vl4, stV + 16384 + off);
                    mma_bf16(cacc[2 * p],     pah, vh4[0], vh4[1]);
                    mma_bf16(cacc[2 * p],     pah, vl4[0], vl4[1]);
                    mma_bf16(cacc[2 * p],     pal, vh4[0], vh4[1]);
                    mma_bf16(cacc[2 * p + 1], pah, vh4[2], vh4[3]);
                    mma_bf16(cacc[2 * p + 1], pah, vl4[2], vl4[3]);
                    mma_bf16(cacc[2 * p + 1], pal, vh4[2], vh4[3]);
                }
            }
        }
    }

    // ---- epilogue: normalize, split, store ----
    float inv0 = 1.f / l0, inv1 = 1.f / l1;
    size_t tok0 = (size_t)(b * SEQ) + t0 + w * 16 + (lane >> 2);
    size_t tok1 = tok0 + 8;
#pragma unroll
    for (int n = 0; n < 16; n++) {
        int col = hh * HD + n * 8 + 2 * (lane & 3);
        float v0 = cacc[n][0] * inv0, v1 = cacc[n][1] * inv0;
        float v2 = cacc[n][2] * inv1, v3 = cacc[n][3] * inv1;
        uint32_t h0 = pack_bf16(v0, v1);
        uint32_t h1 = pack_bf16(v2, v3);
        __nv_bfloat162* hp;
        hp = (__nv_bfloat162*)&h0;
        uint32_t lo0 = pack_bf16(v0 - __bfloat162float(hp->x), v1 - __bfloat162float(hp->y));
        hp = (__nv_bfloat162*)&h1;
        uint32_t lo1 = pack_bf16(v2 - __bfloat162float(hp->x), v3 - __bfloat162float(hp->y));
        *(uint32_t*)&oh[tok0 * QD + col] = h0;
        *(uint32_t*)&ol[tok0 * QD + col] = lo0;
        *(uint32_t*)&oh[tok1 * QD + col] = h1;
        *(uint32_t*)&ol[tok1 * QD + col] = lo1;
    }
}

// ---------------- RoPE tables ----------------
__global__ void rope_table_kernel(float* __restrict__ cost, float* __restrict__ sint) {
    int pos = blockIdx.x;
    int i   = threadIdx.x;
    float invf = (float)pow(1000000.0, -(double)i / 64.0);
    float angf = (float)pos * invf;
    double ang = (double)angf;
    cost[pos * 64 + i] = (float)cos(ang);
    sint[pos * 64 + i] = (float)sin(ang);
}

// ---------------- Embedding gather ----------------
__global__ void embed_kernel(const int* __restrict__ ids,
                             const float* __restrict__ emb,
                             float* __restrict__ out) {
    int t = blockIdx.x;
    int id = ids[t];
    const float4* src = (const float4*)(emb + (size_t)id * H);
    float4* dst = (float4*)(out + (size_t)t * H);
    for (int i = threadIdx.x; i < H / 4; i += blockDim.x) dst[i] = src[i];
}

// ---------------- Row RMSNorm with fused bf16 hi/lo split ----------------
__global__ void rmsnorm_split_kernel(const float* __restrict__ in,
                                     const float* __restrict__ w,
                                     __nv_bfloat16* __restrict__ oh,
                                     __nv_bfloat16* __restrict__ ol, int W) {
    __shared__ float red[256];
    int row = blockIdx.x;
    const float* x = in + (size_t)row * W;
    float s = 0.f;
    for (int i = threadIdx.x; i < W; i += 256) { float v = x[i]; s += v * v; }
    red[threadIdx.x] = s;
    __syncthreads();
    for (int st = 128; st > 0; st >>= 1) {
        if (threadIdx.x < st) red[threadIdx.x] += red[threadIdx.x + st];
        __syncthreads();
    }
    float rms = rsqrtf(red[0] / (float)W + EPS);
    for (int i = threadIdx.x; i < W; i += 256) {
        float v = x[i] * rms * w[i];
        __nv_bfloat16 hi = __float2bfloat16(v);
        size_t o = (size_t)row * W + i;
        oh[o] = hi;
        ol[o] = __float2bfloat16(v - __bfloat162float(hi));
    }
}

// ---------------- Per-head RMSNorm + RoPE + bf16 hi/lo split ----------------
__global__ void qk_norm_rope_split_kernel(const float* __restrict__ x,
                                          int xstride, int colbase,
                                          const float* __restrict__ w,
                                          const float* __restrict__ cost,
                                          const float* __restrict__ sint,
                                          __nv_bfloat16* __restrict__ oh,
                                          __nv_bfloat16* __restrict__ ol,
                                          int nheads, float scale) {
    __shared__ float sh[HD];
    __shared__ float red[HD];
    int t  = blockIdx.x / nheads;
    int hh = blockIdx.x % nheads;
    int pos = t % SEQ;
    const float* p = x + (size_t)t * xstride + colbase + hh * HD;
    int d = threadIdx.x;
    float v = p[d];
    red[d] = v * v;
    __syncthreads();
    for (int st = 64; st > 0; st >>= 1) {
        if (d < st) red[d] += red[d + st];
        __syncthreads();
    }
    float rms = rsqrtf(red[0] / (float)HD + EPS);
    float xn = v * rms * w[d];
    sh[d] = xn;
    __syncthreads();
    int fi = d & 63;
    float c = cost[pos * 64 + fi];
    float s = sint[pos * 64 + fi];
    float other = (d < 64) ? -sh[d + 64] : sh[d - 64];
    float val = (xn * c + other * s) * scale;
    __nv_bfloat16 hi = __float2bfloat16(val);
    size_t o = ((size_t)t * nheads + hh) * HD + d;
    oh[o] = hi;
    ol[o] = __float2bfloat16(val - __bfloat162float(hi));
}

// ---------------- SiLU(g) * u from fused GU buffer, with bf16 hi/lo split ------------
__global__ void silu_mul_split_kernel(const float* __restrict__ gu,
                                      __nv_bfloat16* __restrict__ oh,
                                      __nv_bfloat16* __restrict__ ol, size_t n) {
    size_t i = (size_t)blockIdx.x * blockDim.x + threadIdx.x;
    if (i < n) {
        size_t t = i / IDIM, j = i % IDIM;
        float x = gu[t * (2 * IDIM) + j];
        float u = gu[t * (2 * IDIM) + IDIM + j];
        float val = (x / (1.f + __expf(-x))) * u;
        __nv_bfloat16 hi = __float2bfloat16(val);
        oh[i] = hi;
        ol[i] = __float2bfloat16(val - __bfloat162float(hi));
    }
}

// ---------------- Host orchestration ----------------
static void launch_gemm3(const __nv_bfloat16* Ah, const __nv_bfloat16* Al,
                         const __nv_bfloat16* Bh, const __nv_bfloat16* Bl,
                         float* C, __nv_bfloat16* Oh, __nv_bfloat16* Ol,
                         int M, int N, int K, int mode) {
    dim3 grid(N / 128, M / 128);
    gemm_mma_kernel<<<grid, 256, GSM_TOTAL>>>(Ah, Al, Bh, Bl, C, Oh, Ol, M, N, K, mode);
}

extern "C" void kernel_launch(void* const* d_in, const int* in_sizes, int n_in,
                              void* d_out, int out_size) {
    const int*   input_ids = (const int*)  d_in[0];
    const float* embed     = (const float*)d_in[1];
    const float* Wq        = (const float*)d_in[2];
    const float* Wk        = (const float*)d_in[3];
    const float* Wv        = (const float*)d_in[4];
    const float* Wo        = (const float*)d_in[5];
    const float* qn        = (const float*)d_in[6];
    const float* kn        = (const float*)d_in[7];
    const float* ln1       = (const float*)d_in[8];
    const float* ln2       = (const float*)d_in[9];
    const float* Wg        = (const float*)d_in[10];
    const float* Wu        = (const float*)d_in[11];
    const float* Wd        = (const float*)d_in[12];
    const float* norm_w    = (const float*)d_in[13];
    const float* lm_head   = (const float*)d_in[14];
    float* out = (float*)d_out;

    float *h, *qk, *gu, *cost, *sint;
    __nv_bfloat16 *wth, *wtl, *ah, *al, *qh, *ql, *kh, *kl, *vth, *vtl;
    cudaGetSymbolAddress((void**)&h,    g_h);
    cudaGetSymbolAddress((void**)&qk,   g_qk);
    cudaGetSymbolAddress((void**)&gu,   g_gu);
    cudaGetSymbolAddress((void**)&cost, g_cos);
    cudaGetSymbolAddress((void**)&sint, g_sin);
    cudaGetSymbolAddress((void**)&wth,  g_wT_hi);
    cudaGetSymbolAddress((void**)&wtl,  g_wT_lo);
    cudaGetSymbolAddress((void**)&ah,   g_a_hi);
    cudaGetSymbolAddress((void**)&al,   g_a_lo);
    cudaGetSymbolAddress((void**)&qh,   g_qh);
    cudaGetSymbolAddress((void**)&ql,   g_ql);
    cudaGetSymbolAddress((void**)&kh,   g_kh);
    cudaGetSymbolAddress((void**)&kl,   g_kl);
    cudaGetSymbolAddress((void**)&vth,  g_vth);
    cudaGetSymbolAddress((void**)&vtl,  g_vtl);

    cudaFuncSetAttribute(gemm_mma_kernel,
                         cudaFuncAttributeMaxDynamicSharedMemorySize, GSM_TOTAL);
    cudaFuncSetAttribute(flash_attn_tc_kernel,
                         cudaFuncAttributeMaxDynamicSharedMemorySize, ASM_BYTES);

    // Launch #1
    embed_kernel<<<TOK, 256>>>(input_ids, embed, h);

    for (int l = 0; l < LNUM; l++) {
        const float* wq = Wq + (size_t)l * H * QD;
        const float* wk = Wk + (size_t)l * H * KVD;
        const float* wv = Wv + (size_t)l * H * KVD;
        const float* wo = Wo + (size_t)l * QD * H;
        const float* wg = Wg + (size_t)l * H * IDIM;
        const float* wu = Wu + (size_t)l * H * IDIM;
        const float* wd = Wd + (size_t)l * IDIM * H;

        // ---- Attention block ----
        rmsnorm_split_kernel<<<TOK, 256>>>(h, ln1 + (size_t)l * H, ah, al, H);        // #2 (l=0)
        convT2_kernel<<<dim3((QD + KVD) / 64, H / 64), 256>>>(wq, wk, wth + WQK, wtl + WQK,
                                                              H, QD, KVD);            // #3
        launch_gemm3(ah, al, wth + WQK, wtl + WQK, qk, 0, 0, TOK, QD + KVD, H, 0);    // #4 <- profiled
        if (l == 0) rope_table_kernel<<<SEQ, 64>>>(cost, sint);                       // #5
        convT2_kernel<<<dim3(KVD / 64, H / 64), 256>>>(wv, wv, wth + WV, wtl + WV,
                                                       H, KVD, 0);
        launch_gemm3(ah, al, wth + WV, wtl + WV, 0, vth, vtl, TOK, KVD, H, 2);
        qk_norm_rope_split_kernel<<<TOK * NH,  HD>>>(qk, QD + KVD, 0,  qn + (size_t)l * HD,
                                                     cost, sint, qh, ql, NH,  ATT_SCALE);
        qk_norm_rope_split_kernel<<<TOK * NKV, HD>>>(qk, QD + KVD, QD, kn + (size_t)l * HD,
                                                     cost, sint, kh, kl, NKV, 1.0f);
        flash_attn_tc_kernel<<<BATCH * NH * (SEQ / 128), 256, ASM_BYTES>>>(
            qh, ql, kh, kl, vth, vtl, ah, al);
        convT2_kernel<<<dim3(H / 64, QD / 64), 256>>>(wo, wo, wth + WO, wtl + WO,
                                                      QD, H, 0);
        launch_gemm3(ah, al, wth + WO, wtl + WO, h, 0, 0, TOK, H, QD, 1);

        // ---- MLP block ----
        rmsnorm_split_kernel<<<TOK, 256>>>(h, ln2 + (size_t)l * H, ah, al, H);
        convT2_kernel<<<dim3(2 * IDIM / 64, H / 64), 256>>>(wg, wu, wth + WGU, wtl + WGU,
                                                            H, IDIM, IDIM);
        launch_gemm3(ah, al, wth + WGU, wtl + WGU, gu, 0, 0, TOK, 2 * IDIM, H, 0);
        {
            size_t n = (size_t)TOK * IDIM;
            silu_mul_split_kernel<<<(unsigned)((n + 255) / 256), 256>>>(gu, ah, al, n);
        }
        convT2_kernel<<<dim3(H / 64, IDIM / 64), 256>>>(wd, wd, wth + WD, wtl + WD,
                                                        IDIM, H, 0);
        launch_gemm3(ah, al, wth + WD, wtl + WD, h, 0, 0, TOK, H, IDIM, 1);
    }

    // ---- Final norm + LM head ----
    rmsnorm_split_kernel<<<TOK, 256>>>(h, norm_w, ah, al, H);
    convT2_kernel<<<dim3(VOC / 64, H / 64), 256>>>(lm_head, lm_head, wth, wtl, H, VOC, 0);
    launch_gemm3(ah, al, wth, wtl, out, 0, 0, TOK, VOC, H, 0);
}

// round 14
// speedup vs baseline: 1.1182x; 1.1182x over previous
#include <cuda_runtime.h>
#include <cuda_bf16.h>
#include <math.h>
#include <stdint.h>

// ---------------- Model constants ----------------
#define LNUM 8
#define H    1024
#define NH   16
#define NKV  8
#define HD   128
#define IDIM 3072
#define VOC  32000
#define BATCH 2
#define SEQ  1024
#define TOK  (BATCH*SEQ)          // 2048
#define QD   (NH*HD)              // 2048
#define KVD  (NKV*HD)             // 1024
#define EPS  1e-6f
#define ATT_SCALE 0.08838834764831845f

// Per-layer transposed-weight offsets (bf16 hi/lo arrays, [N][K] layout)
#define OWQ 0
#define OWK (OWQ + QD*H)
#define OWV (OWK + KVD*H)
#define OWO (OWV + KVD*H)
#define OWG (OWO + H*QD)
#define OWU (OWG + (size_t)IDIM*H)
#define OWD (OWU + (size_t)IDIM*H)
#define PLSZ (OWD + (size_t)H*IDIM)
#define OLM  ((size_t)LNUM * PLSZ)
#define WT_TOTAL (OLM + (size_t)VOC*H)

// ---------------- Scratch (device globals; no allocation allowed) ----------------
__device__ float g_h  [(size_t)TOK * H];
__device__ float g_q  [(size_t)TOK * QD];
__device__ float g_k  [(size_t)TOK * KVD];
__device__ float g_mg [(size_t)TOK * IDIM];
__device__ float g_mu [(size_t)TOK * IDIM];
__device__ float g_cos[(size_t)SEQ * 64];
__device__ float g_sin[(size_t)SEQ * 64];
__device__ __nv_bfloat16 g_wT_hi[WT_TOTAL];
__device__ __nv_bfloat16 g_wT_lo[WT_TOTAL];
__device__ __nv_bfloat16 g_a_hi[(size_t)TOK * IDIM];
__device__ __nv_bfloat16 g_a_lo[(size_t)TOK * IDIM];
__device__ __nv_bfloat16 g_qh[(size_t)TOK * QD];
__device__ __nv_bfloat16 g_ql[(size_t)TOK * QD];
__device__ __nv_bfloat16 g_kh[(size_t)TOK * KVD];
__device__ __nv_bfloat16 g_kl[(size_t)TOK * KVD];
__device__ __nv_bfloat16 g_vth[(size_t)TOK * KVD];   // [b][kvh][dim][seq]
__device__ __nv_bfloat16 g_vtl[(size_t)TOK * KVD];

// ---------------- PTX helpers ----------------
__device__ __forceinline__ uint32_t smem_to_u32(const void* p) {
    uint32_t a;
    asm("{ .reg .u64 t; cvta.to.shared.u64 t, %1; cvt.u32.u64 %0, t; }" : "=r"(a) : "l"(p));
    return a;
}
__device__ __forceinline__ void cp16(uint32_t s, const void* g) {
    asm volatile("cp.async.cg.shared.global [%0], [%1], 16;" :: "r"(s), "l"(g));
}
__device__ __forceinline__ void ldsm4(uint32_t* r, uint32_t addr) {
    asm volatile("ldmatrix.sync.aligned.m8n8.x4.shared.b16 {%0,%1,%2,%3}, [%4];"
                 : "=r"(r[0]), "=r"(r[1]), "=r"(r[2]), "=r"(r[3]) : "r"(addr));
}
__device__ __forceinline__ void mma_bf16(float* c, const uint32_t* a, uint32_t b0, uint32_t b1) {
    asm volatile("mma.sync.aligned.m16n8k16.row.col.f32.bf16.bf16.f32 "
                 "{%0,%1,%2,%3}, {%4,%5,%6,%7}, {%8,%9}, {%0,%1,%2,%3};"
                 : "+f"(c[0]), "+f"(c[1]), "+f"(c[2]), "+f"(c[3])
                 : "r"(a[0]), "r"(a[1]), "r"(a[2]), "r"(a[3]), "r"(b0), "r"(b1));
}
#define SWZ(off) ((off) ^ (((off) >> 3) & 0x70))

__device__ __forceinline__ uint32_t pack_bf16(float a, float b) {
    __nv_bfloat162 h;
    h.x = __float2bfloat16(a);
    h.y = __float2bfloat16(b);
    return *(uint32_t*)&h;
}

// ---------------- Weight transpose + hi/lo bf16 split: W[KxN] -> T[N][K] ------------
__global__ __launch_bounds__(256) void convT_kernel(const float* __restrict__ W,
                                                    __nv_bfloat16* __restrict__ Th,
                                                    __nv_bfloat16* __restrict__ Tl,
                                                    int K, int N) {
    __shared__ float sm[64][65];
    int n0 = blockIdx.x * 64, k0 = blockIdx.y * 64;
    int t = threadIdx.x;
    int rr = t >> 4, cc = (t & 15) * 4;
#pragma unroll
    for (int it = 0; it < 4; it++) {
        int kr = rr + it * 16;
        float4 v = *(const float4*)&W[(size_t)(k0 + kr) * N + n0 + cc];
        sm[kr][cc + 0] = v.x;  sm[kr][cc + 1] = v.y;
        sm[kr][cc + 2] = v.z;  sm[kr][cc + 3] = v.w;
    }
    __syncthreads();
#pragma unroll
    for (int it = 0; it < 4; it++) {
        int nr = rr + it * 16;
        float v0 = sm[cc + 0][nr], v1 = sm[cc + 1][nr];
        float v2 = sm[cc + 2][nr], v3 = sm[cc + 3][nr];
        __nv_bfloat16 h0 = __float2bfloat16(v0), h1 = __float2bfloat16(v1);
        __nv_bfloat16 h2 = __float2bfloat16(v2), h3 = __float2bfloat16(v3);
        uint32_t hp0 = pack_bf16(v0, v1), hp1 = pack_bf16(v2, v3);
        uint32_t lp0 = pack_bf16(v0 - __bfloat162float(h0), v1 - __bfloat162float(h1));
        uint32_t lp1 = pack_bf16(v2 - __bfloat162float(h2), v3 - __bfloat162float(h3));
        size_t o = (size_t)(n0 + nr) * K + k0 + cc;
        *(uint2*)&Th[o] = make_uint2(hp0, hp1);
        *(uint2*)&Tl[o] = make_uint2(lp0, lp1);
    }
}

// ---------------- bf16x3 GEMM via mma.sync: C = A @ B^T (B stored [N][K]) -----------
// 128x64 CTA tile, 8 warps (4x2), warp tile 32x32, BK=64, 2-stage cp.async,
// 1 barrier/iter, 96KB smem -> 2 CTAs/SM.
// Stage layout: Ah 0 | Al 16K | Bh 32K | Bl 40K   (STG = 48K)
#define STG 49152
#define GSM_TOTAL (2 * STG)
__global__ __launch_bounds__(256, 2) void gemm_mma_kernel(
    const __nv_bfloat16* __restrict__ Ah, const __nv_bfloat16* __restrict__ Al,
    const __nv_bfloat16* __restrict__ Bh, const __nv_bfloat16* __restrict__ Bl,
    float* __restrict__ C, __nv_bfloat16* __restrict__ Oh, __nv_bfloat16* __restrict__ Ol,
    int M, int N, int K, int mode) {
    extern __shared__ char smem[];
    uint32_t sb = smem_to_u32(smem);
    int tid = threadIdx.x, lane = tid & 31, wid = tid >> 5;
    int brow = blockIdx.y * 128, bcol = blockIdx.x * 64;
    int wm = wid & 3, wn = wid >> 2;       // 4 row-strips x 2 col-strips of 32

    float acc[2][4][4] = {};
    int T = K >> 6;

    auto issue_loads = [&](int t) {
        uint32_t st = sb + (uint32_t)(t & 1) * STG;
        int k0 = t << 6;
#pragma unroll
        for (int i = 0; i < 4; i++) {       // A: 128 rows x 64 cols, hi+lo
            int idx = tid + i * 256;        // 0..1023
            int r = idx >> 3, g = idx & 7;
            uint32_t off = SWZ((uint32_t)(r * 128 + g * 16));
            size_t ga = (size_t)(brow + r) * K + k0 + g * 8;
            cp16(st + off,         Ah + ga);
            cp16(st + 16384 + off, Al + ga);
        }
#pragma unroll
        for (int i = 0; i < 2; i++) {       // B: 64 rows x 64 cols, hi+lo
            int idx = tid + i * 256;        // 0..511
            int r = idx >> 3, g = idx & 7;
            uint32_t off = SWZ((uint32_t)(r * 128 + g * 16));
            size_t gb = (size_t)(bcol + r) * K + k0 + g * 8;
            cp16(st + 32768 + off, Bh + gb);
            cp16(st + 40960 + off, Bl + gb);
        }
        asm volatile("cp.async.commit_group;");
    };

    issue_loads(0);

    uint32_t a_roff = (uint32_t)(wm * 32 + (lane & 15));
    uint32_t a_koff = (uint32_t)((lane >> 4) * 8);
    uint32_t b_noff = (uint32_t)(wn * 32 + ((lane >> 4) * 8) + (lane & 7));
    uint32_t b_koff = (uint32_t)(((lane >> 3) & 1) * 8);

    for (int t = 0; t < T; t++) {
        asm volatile("cp.async.wait_group 0;");
        __syncthreads();
        if (t + 1 < T) issue_loads(t + 1);
        uint32_t st = sb + (uint32_t)(t & 1) * STG;
#pragma unroll
        for (int kk = 0; kk < 4; kk++) {
            uint32_t ah_[2][4], al_[2][4];
#pragma unroll
            for (int mi = 0; mi < 2; mi++) {
                uint32_t off = SWZ((a_roff + mi * 16) * 128 + (kk * 16 + a_koff) * 2);
                ldsm4(ah_[mi], st + off);
                ldsm4(al_[mi], st + 16384 + off);
            }
            uint32_t bh_[2][4], bl_[2][4];
#pragma unroll
            for (int p = 0; p < 2; p++) {
                uint32_t off = SWZ((b_noff + p * 16) * 128 + (kk * 16 + b_koff) * 2);
                ldsm4(bh_[p], st + 32768 + off);
                ldsm4(bl_[p], st + 40960 + off);
            }
#pragma unroll
            for (int mi = 0; mi < 2; mi++)
#pragma unroll
                for (int ni = 0; ni < 4; ni++) {
                    int p = ni >> 1, q2 = (ni & 1) * 2;
                    mma_bf16(acc[mi][ni], ah_[mi], bh_[p][q2], bh_[p][q2 + 1]);
                    mma_bf16(acc[mi][ni], ah_[mi], bl_[p][q2], bl_[p][q2 + 1]);
                    mma_bf16(acc[mi][ni], al_[mi], bh_[p][q2], bh_[p][q2 + 1]);
                }
        }
    }

#pragma unroll
    for (int mi = 0; mi < 2; mi++)
#pragma unroll
        for (int ni = 0; ni < 4; ni++) {
            int r0 = brow + wm * 32 + mi * 16 + (lane >> 2);
            int c0 = bcol + wn * 32 + ni * 8 + 2 * (lane & 3);
            float* a4 = acc[mi][ni];
            if (mode == 2) {
#pragma unroll
                for (int e = 0; e < 4; e++) {
                    int r = r0 + (e >> 1) * 8;
                    int c = c0 + (e & 1);
                    int b = r >> 10, seq = r & 1023;
                    int kvh = c >> 7, hd = c & 127;
                    size_t idx = ((size_t)((b * NKV + kvh) * HD + hd)) * SEQ + seq;
                    float v = a4[e];
                    __nv_bfloat16 hi = __float2bfloat16(v);
                    Oh[idx] = hi;
                    Ol[idx] = __float2bfloat16(v - __bfloat162float(hi));
                }
            } else {
                float2* p0 = (float2*)(C + (size_t)r0 * N + c0);
                float2* p1 = (float2*)(C + (size_t)(r0 + 8) * N + c0);
                if (mode == 1) {
                    float2 v0 = *p0, v1 = *p1;
                    v0.x += a4[0]; v0.y += a4[1];
                    v1.x += a4[2]; v1.y += a4[3];
                    *p0 = v0; *p1 = v1;
                } else {
                    *p0 = make_float2(a4[0], a4[1]);
                    *p1 = make_float2(a4[2], a4[3]);
                }
            }
        }
}

// ---------------- Tensor-core flash attention (round-8 known good) ------------------
// Block: (b, h, 64-query tile). 4 warps, warp owns 16 q rows. K-tiles of 64 keys.
// smem: QH 0 | QL 16K | KH 32K | KL 48K | VH 64K | VL 80K  (96KB total)
#define ASM_BYTES 98304
__global__ __launch_bounds__(128, 2) void flash_attn_tc_kernel(
    const __nv_bfloat16* __restrict__ qh, const __nv_bfloat16* __restrict__ ql,
    const __nv_bfloat16* __restrict__ kh, const __nv_bfloat16* __restrict__ kl,
    const __nv_bfloat16* __restrict__ vth, const __nv_bfloat16* __restrict__ vtl,
    __nv_bfloat16* __restrict__ oh, __nv_bfloat16* __restrict__ ol) {
    extern __shared__ char smem[];
    uint32_t sb = smem_to_u32(smem);
    int tid = threadIdx.x, lane = tid & 31, w = tid >> 5;
    int gid = blockIdx.x;
    int qt = gid & 15, hh = (gid >> 4) & 15, b = gid >> 8;
    int t0 = qt * 64;
    int kvh = hh >> 1;

    for (int i = tid; i < 1024; i += 128) {
        int c = i >> 9, r = (i >> 3) & 63, g = i & 7;
        uint32_t off = c * 8192 + SWZ((uint32_t)(r * 128 + g * 16));
        size_t gq = ((size_t)(b * SEQ + t0 + r) * NH + hh) * HD + c * 64 + g * 8;
        cp16(sb + off,         qh + gq);
        cp16(sb + 16384 + off, ql + gq);
    }
    asm volatile("cp.async.commit_group;");
    asm volatile("cp.async.wait_group 0;");
    __syncthreads();

    uint32_t qah[2][4][4], qal[2][4][4];
#pragma unroll
    for (int c = 0; c < 2; c++)
#pragma unroll
        for (int kk = 0; kk < 4; kk++) {
            uint32_t off = c * 8192 +
                SWZ((uint32_t)((w * 16 + (lane & 15)) * 128 + (kk * 16 + (lane >> 4) * 8) * 2));
            ldsm4(qah[c][kk], sb + off);
            ldsm4(qal[c][kk], sb + 16384 + off);
        }

    float cacc[16][4] = {};
    float m0 = -1e30f, m1 = -1e30f, l0 = 0.f, l1 = 0.f;
    int r0g = t0 + w * 16 + (lane >> 2);
    int r1g = r0g + 8;

    for (int j0 = 0; j0 <= t0; j0 += 64) {
        for (int i = tid; i < 1024; i += 128) {
            int c = i >> 9, r = (i >> 3) & 63, g = i & 7;
            uint32_t koff = c * 8192 + SWZ((uint32_t)(r * 128 + g * 16));
            size_t gk = ((size_t)(b * SEQ + j0 + r) * NKV + kvh) * HD + c * 64 + g * 8;
            cp16(sb + 32768 + koff, kh + gk);
            cp16(sb + 49152 + koff, kl + gk);
            int dim = i >> 3, g2 = i & 7;
            uint32_t voff = SWZ((uint32_t)(dim * 128 + g2 * 16));
            size_t gv = ((size_t)((b * NKV + kvh) * HD + dim)) * SEQ + j0 + g2 * 8;
            cp16(sb + 65536 + voff, vth + gv);
            cp16(sb + 81920 + voff, vtl + gv);
        }
        asm volatile("cp.async.commit_group;");
        asm volatile("cp.async.wait_group 0;");
        __syncthreads();

        float sacc[8][4] = {};
#pragma unroll
        for (int c = 0; c < 2; c++)
#pragma unroll
            for (int kk = 0; kk < 4; kk++) {
#pragma unroll
                for (int p = 0; p < 4; p++) {
                    uint32_t off = c * 8192 +
                        SWZ((uint32_t)((p * 16 + (lane >> 4) * 8 + (lane & 7)) * 128 +
                                       (kk * 16 + ((lane >> 3) & 1) * 8) * 2));
                    uint32_t bh4[4], bl4[4];
                    ldsm4(bh4, sb + 32768 + off);
                    ldsm4(bl4, sb + 49152 + off);
                    mma_bf16(sacc[2 * p],     qah[c][kk], bh4[0], bh4[1]);
                    mma_bf16(sacc[2 * p],     qah[c][kk], bl4[0], bl4[1]);
                    mma_bf16(sacc[2 * p],     qal[c][kk], bh4[0], bh4[1]);
                    mma_bf16(sacc[2 * p + 1], qah[c][kk], bh4[2], bh4[3]);
                    mma_bf16(sacc[2 * p + 1], qah[c][kk], bl4[2], bl4[3]);
                    mma_bf16(sacc[2 * p + 1], qal[c][kk], bh4[2], bh4[3]);
                }
            }

        if (j0 == t0) {
#pragma unroll
            for (int ni = 0; ni < 8; ni++) {
                int colb = j0 + ni * 8 + 2 * (lane & 3);
                if (colb     > r0g) sacc[ni][0] = -1e30f;
                if (colb + 1 > r0g) sacc[ni][1] = -1e30f;
                if (colb     > r1g) sacc[ni][2] = -1e30f;
                if (colb + 1 > r1g) sacc[ni][3] = -1e30f;
            }
        }

        float rmax0 = -1e30f, rmax1 = -1e30f;
#pragma unroll
        for (int ni = 0; ni < 8; ni++) {
            rmax0 = fmaxf(rmax0, fmaxf(sacc[ni][0], sacc[ni][1]));
            rmax1 = fmaxf(rmax1, fmaxf(sacc[ni][2], sacc[ni][3]));
        }
        rmax0 = fmaxf(rmax0, __shfl_xor_sync(0xffffffffu, rmax0, 1));
        rmax0 = fmaxf(rmax0, __shfl_xor_sync(0xffffffffu, rmax0, 2));
        rmax1 = fmaxf(rmax1, __shfl_xor_sync(0xffffffffu, rmax1, 1));
        rmax1 = fmaxf(rmax1, __shfl_xor_sync(0xffffffffu, rmax1, 2));
        float mn0 = fmaxf(m0, rmax0), mn1 = fmaxf(m1, rmax1);
        float corr0 = __expf(m0 - mn0), corr1 = __expf(m1 - mn1);
        float rs0 = 0.f, rs1 = 0.f;
#pragma unroll
        for (int ni = 0; ni < 8; ni++) {
            sacc[ni][0] = __expf(sacc[ni][0] - mn0);
            sacc[ni][1] = __expf(sacc[ni][1] - mn0);
            sacc[ni][2] = __expf(sacc[ni][2] - mn1);
            sacc[ni][3] = __expf(sacc[ni][3] - mn1);
            rs0 += sacc[ni][0] + sacc[ni][1];
            rs1 += sacc[ni][2] + sacc[ni][3];
        }
        rs0 += __shfl_xor_sync(0xffffffffu, rs0, 1);
        rs0 += __shfl_xor_sync(0xffffffffu, rs0, 2);
        rs1 += __shfl_xor_sync(0xffffffffu, rs1, 1);
        rs1 += __shfl_xor_sync(0xffffffffu, rs1, 2);
        l0 = l0 * corr0 + rs0;  m0 = mn0;
        l1 = l1 * corr1 + rs1;  m1 = mn1;
#pragma unroll
        for (int n = 0; n < 16; n++) {
            cacc[n][0] *= corr0; cacc[n][1] *= corr0;
            cacc[n][2] *= corr1; cacc[n][3] *= corr1;
        }

#pragma unroll
        for (int kk = 0; kk < 4; kk++) {
            uint32_t pah[4], pal[4];
            float* s0 = sacc[2 * kk];
            float* s1 = sacc[2 * kk + 1];
            pah[0] = pack_bf16(s0[0], s0[1]);
            pah[1] = pack_bf16(s0[2], s0[3]);
            pah[2] = pack_bf16(s1[0], s1[1]);
            pah[3] = pack_bf16(s1[2], s1[3]);
            {
                __nv_bfloat162* hx;
                hx = (__nv_bfloat162*)&pah[0];
                pal[0] = pack_bf16(s0[0] - __bfloat162float(hx->x), s0[1] - __bfloat162float(hx->y));
                hx = (__nv_bfloat162*)&pah[1];
                pal[1] = pack_bf16(s0[2] - __bfloat162float(hx->x), s0[3] - __bfloat162float(hx->y));
                hx = (__nv_bfloat162*)&pah[2];
                pal[2] = pack_bf16(s1[0] - __bfloat162float(hx->x), s1[1] - __bfloat162float(hx->y));
                hx = (__nv_bfloat162*)&pah[3];
                pal[3] = pack_bf16(s1[2] - __bfloat162float(hx->x), s1[3] - __bfloat162float(hx->y));
            }
#pragma unroll
            for (int p = 0; p < 8; p++) {
                uint32_t off = SWZ((uint32_t)((p * 16 + (lane >> 4) * 8 + (lane & 7)) * 128 +
                                              (kk * 16 + ((lane >> 3) & 1) * 8) * 2));
                uint32_t vh4[4], vl4[4];
                ldsm4(vh4, sb + 65536 + off);
                ldsm4(vl4, sb + 81920 + off);
                mma_bf16(cacc[2 * p],     pah, vh4[0], vh4[1]);
                mma_bf16(cacc[2 * p],     pah, vl4[0], vl4[1]);
                mma_bf16(cacc[2 * p],     pal, vh4[0], vh4[1]);
                mma_bf16(cacc[2 * p + 1], pah, vh4[2], vh4[3]);
                mma_bf16(cacc[2 * p + 1], pah, vl4[2], vl4[3]);
                mma_bf16(cacc[2 * p + 1], pal, vh4[2], vh4[3]);
            }
        }
        __syncthreads();
    }

    float inv0 = 1.f / l0, inv1 = 1.f / l1;
    size_t tok0 = (size_t)(b * SEQ) + t0 + w * 16 + (lane >> 2);
    size_t tok1 = tok0 + 8;
#pragma unroll
    for (int n = 0; n < 16; n++) {
        int col = hh * HD + n * 8 + 2 * (lane & 3);
        float v0 = cacc[n][0] * inv0, v1 = cacc[n][1] * inv0;
        float v2 = cacc[n][2] * inv1, v3 = cacc[n][3] * inv1;
        uint32_t h0 = pack_bf16(v0, v1);
        uint32_t h1 = pack_bf16(v2, v3);
        __nv_bfloat162* hp;
        hp = (__nv_bfloat162*)&h0;
        uint32_t lo0 = pack_bf16(v0 - __bfloat162float(hp->x), v1 - __bfloat162float(hp->y));
        hp = (__nv_bfloat162*)&h1;
        uint32_t lo1 = pack_bf16(v2 - __bfloat162float(hp->x), v3 - __bfloat162float(hp->y));
        *(uint32_t*)&oh[tok0 * QD + col] = h0;
        *(uint32_t*)&ol[tok0 * QD + col] = lo0;
        *(uint32_t*)&oh[tok1 * QD + col] = h1;
        *(uint32_t*)&ol[tok1 * QD + col] = lo1;
    }
}

// ---------------- RoPE tables ----------------
__global__ void rope_table_kernel(float* __restrict__ cost, float* __restrict__ sint) {
    int pos = blockIdx.x;
    int i   = threadIdx.x;
    float invf = (float)pow(1000000.0, -(double)i / 64.0);
    float angf = (float)pos * invf;
    double ang = (double)angf;
    cost[pos * 64 + i] = (float)cos(ang);
    sint[pos * 64 + i] = (float)sin(ang);
}

// ---------------- Embedding gather ----------------
__global__ void embed_kernel(const int* __restrict__ ids,
                             const float* __restrict__ emb,
                             float* __restrict__ out) {
    int t = blockIdx.x;
    int id = ids[t];
    const float4* src = (const float4*)(emb + (size_t)id * H);
    float4* dst = (float4*)(out + (size_t)t * H);
    for (int i = threadIdx.x; i < H / 4; i += blockDim.x) dst[i] = src[i];
}

// ---------------- Row RMSNorm with fused bf16 hi/lo split ----------------
__global__ void rmsnorm_split_kernel(const float* __restrict__ in,
                                     const float* __restrict__ w,
                                     __nv_bfloat16* __restrict__ oh,
                                     __nv_bfloat16* __restrict__ ol, int W) {
    __shared__ float red[256];
    int row = blockIdx.x;
    const float* x = in + (size_t)row * W;
    float s = 0.f;
    for (int i = threadIdx.x; i < W; i += 256) { float v = x[i]; s += v * v; }
    red[threadIdx.x] = s;
    __syncthreads();
    for (int st = 128; st > 0; st >>= 1) {
        if (threadIdx.x < st) red[threadIdx.x] += red[threadIdx.x + st];
        __syncthreads();
    }
    float rms = rsqrtf(red[0] / (float)W + EPS);
    for (int i = threadIdx.x; i < W; i += 256) {
        float v = x[i] * rms * w[i];
        __nv_bfloat16 hi = __float2bfloat16(v);
        size_t o = (size_t)row * W + i;
        oh[o] = hi;
        ol[o] = __float2bfloat16(v - __bfloat162float(hi));
    }
}

// ---------------- Per-head RMSNorm + RoPE + bf16 hi/lo split ----------------
__global__ void qk_norm_rope_split_kernel(const float* __restrict__ x,
                                          const float* __restrict__ w,
                                          const float* __restrict__ cost,
                                          const float* __restrict__ sint,
                                          __nv_bfloat16* __restrict__ oh,
                                          __nv_bfloat16* __restrict__ ol,
                                          int nheads, float scale) {
    __shared__ float sh[HD];
    __shared__ float red[HD];
    int t  = blockIdx.x / nheads;
    int hh = blockIdx.x % nheads;
    int pos = t % SEQ;
    const float* p = x + ((size_t)t * nheads + hh) * HD;
    int d = threadIdx.x;
    float v = p[d];
    red[d] = v * v;
    __syncthreads();
    for (int st = 64; st > 0; st >>= 1) {
        if (d < st) red[d] += red[d + st];
        __syncthreads();
    }
    float rms = rsqrtf(red[0] / (float)HD + EPS);
    float xn = v * rms * w[d];
    sh[d] = xn;
    __syncthreads();
    int fi = d & 63;
    float c = cost[pos * 64 + fi];
    float s = sint[pos * 64 + fi];
    float other = (d < 64) ? -sh[d + 64] : sh[d - 64];
    float val = (xn * c + other * s) * scale;
    __nv_bfloat16 hi = __float2bfloat16(val);
    size_t o = ((size_t)t * nheads + hh) * HD + d;
    oh[o] = hi;
    ol[o] = __float2bfloat16(val - __bfloat162float(hi));
}

// ---------------- SiLU(g) * u with fused bf16 hi/lo split ----------------
__global__ void silu_mul_split_kernel(const float* __restrict__ g,
                                      const float* __restrict__ u,
                                      __nv_bfloat16* __restrict__ oh,
                                      __nv_bfloat16* __restrict__ ol, size_t n) {
    size_t i = (size_t)blockIdx.x * blockDim.x + threadIdx.x;
    if (i < n) {
        float x = g[i];
        float val = (x / (1.f + __expf(-x))) * u[i];
        __nv_bfloat16 hi = __float2bfloat16(val);
        oh[i] = hi;
        ol[i] = __float2bfloat16(val - __bfloat162float(hi));
    }
}

// ---------------- Host orchestration ----------------
static void launch_gemm3(const __nv_bfloat16* Ah, const __nv_bfloat16* Al,
                         const __nv_bfloat16* Bh, const __nv_bfloat16* Bl,
                         float* C, __nv_bfloat16* Oh, __nv_bfloat16* Ol,
                         int M, int N, int K, int mode) {
    dim3 grid(N / 64, M / 128);
    gemm_mma_kernel<<<grid, 256, GSM_TOTAL>>>(Ah, Al, Bh, Bl, C, Oh, Ol, M, N, K, mode);
}

extern "C" void kernel_launch(void* const* d_in, const int* in_sizes, int n_in,
                              void* d_out, int out_size) {
    const int*   input_ids = (const int*)  d_in[0];
    const float* embed     = (const float*)d_in[1];
    const float* Wq        = (const float*)d_in[2];
    const float* Wk        = (const float*)d_in[3];
    const float* Wv        = (const float*)d_in[4];
    const float* Wo        = (const float*)d_in[5];
    const float* qn        = (const float*)d_in[6];
    const float* kn        = (const float*)d_in[7];
    const float* ln1       = (const float*)d_in[8];
    const float* ln2       = (const float*)d_in[9];
    const float* Wg        = (const float*)d_in[10];
    const float* Wu        = (const float*)d_in[11];
    const float* Wd        = (const float*)d_in[12];
    const float* norm_w    = (const float*)d_in[13];
    const float* lm_head   = (const float*)d_in[14];
    float* out = (float*)d_out;

    float *h, *q, *k, *mg, *mu, *cost, *sint;
    __nv_bfloat16 *wth, *wtl, *ah, *al, *qh, *ql, *kh, *kl, *vth, *vtl;
    cudaGetSymbolAddress((void**)&h,    g_h);
    cudaGetSymbolAddress((void**)&q,    g_q);
    cudaGetSymbolAddress((void**)&k,    g_k);
    cudaGetSymbolAddress((void**)&mg,   g_mg);
    cudaGetSymbolAddress((void**)&mu,   g_mu);
    cudaGetSymbolAddress((void**)&cost, g_cos);
    cudaGetSymbolAddress((void**)&sint, g_sin);
    cudaGetSymbolAddress((void**)&wth,  g_wT_hi);
    cudaGetSymbolAddress((void**)&wtl,  g_wT_lo);
    cudaGetSymbolAddress((void**)&ah,   g_a_hi);
    cudaGetSymbolAddress((void**)&al,   g_a_lo);
    cudaGetSymbolAddress((void**)&qh,   g_qh);
    cudaGetSymbolAddress((void**)&ql,   g_ql);
    cudaGetSymbolAddress((void**)&kh,   g_kh);
    cudaGetSymbolAddress((void**)&kl,   g_kl);
    cudaGetSymbolAddress((void**)&vth,  g_vth);
    cudaGetSymbolAddress((void**)&vtl,  g_vtl);

    cudaFuncSetAttribute(gemm_mma_kernel,
                         cudaFuncAttributeMaxDynamicSharedMemorySize, GSM_TOTAL);
    cudaFuncSetAttribute(flash_attn_tc_kernel,
                         cudaFuncAttributeMaxDynamicSharedMemorySize, ASM_BYTES);

    // ---- Weight transpose + bf16 hi/lo split ----
    for (int l = 0; l < LNUM; l++) {
        size_t base = (size_t)l * PLSZ;
        convT_kernel<<<dim3(QD / 64,   H / 64),   256>>>(Wq + (size_t)l * H * QD,   wth + base + OWQ, wtl + base + OWQ, H,   QD);
        convT_kernel<<<dim3(KVD / 64,  H / 64),   256>>>(Wk + (size_t)l * H * KVD,  wth + base + OWK, wtl + base + OWK, H,   KVD);
        convT_kernel<<<dim3(KVD / 64,  H / 64),   256>>>(Wv + (size_t)l * H * KVD,  wth + base + OWV, wtl + base + OWV, H,   KVD);
        convT_kernel<<<dim3(H / 64,    QD / 64),  256>>>(Wo + (size_t)l * QD * H,   wth + base + OWO, wtl + base + OWO, QD,  H);
        convT_kernel<<<dim3(IDIM / 64, H / 64),   256>>>(Wg + (size_t)l * H * IDIM, wth + base + OWG, wtl + base + OWG, H,   IDIM);
        convT_kernel<<<dim3(IDIM / 64, H / 64),   256>>>(Wu + (size_t)l * H * IDIM, wth + base + OWU, wtl + base + OWU, H,   IDIM);
        convT_kernel<<<dim3(H / 64,    IDIM / 64),256>>>(Wd + (size_t)l * IDIM * H, wth + base + OWD, wtl + base + OWD, IDIM,H);
    }
    convT_kernel<<<dim3(VOC / 64, H / 64), 256>>>(lm_head, wth + OLM, wtl + OLM, H, VOC);

    // ---- RoPE tables + embedding ----
    rope_table_kernel<<<SEQ, 64>>>(cost, sint);
    embed_kernel<<<TOK, 256>>>(input_ids, embed, h);

    for (int l = 0; l < LNUM; l++) {
        size_t base = (size_t)l * PLSZ;

        // ---- Attention block ----
        rmsnorm_split_kernel<<<TOK, 256>>>(h, ln1 + (size_t)l * H, ah, al, H);
        launch_gemm3(ah, al, wth + base + OWQ, wtl + base + OWQ, q, 0, 0, TOK, QD,  H, 0);
        launch_gemm3(ah, al, wth + base + OWK, wtl + base + OWK, k, 0, 0, TOK, KVD, H, 0);
        launch_gemm3(ah, al, wth + base + OWV, wtl + base + OWV, 0, vth, vtl, TOK, KVD, H, 2);
        qk_norm_rope_split_kernel<<<TOK * NH,  HD>>>(q, qn + (size_t)l * HD, cost, sint, qh, ql, NH,  ATT_SCALE);
        qk_norm_rope_split_kernel<<<TOK * NKV, HD>>>(k, kn + (size_t)l * HD, cost, sint, kh, kl, NKV, 1.0f);
        flash_attn_tc_kernel<<<BATCH * NH * (SEQ / 64), 128, ASM_BYTES>>>(qh, ql, kh, kl, vth, vtl, ah, al);
        launch_gemm3(ah, al, wth + base + OWO, wtl + base + OWO, h, 0, 0, TOK, H, QD, 1);

        // ---- MLP block ----
        rmsnorm_split_kernel<<<TOK, 256>>>(h, ln2 + (size_t)l * H, ah, al, H);
        launch_gemm3(ah, al, wth + base + OWG, wtl + base + OWG, mg, 0, 0, TOK, IDIM, H, 0);
        launch_gemm3(ah, al, wth + base + OWU, wtl + base + OWU, mu, 0, 0, TOK, IDIM, H, 0);
        {
            size_t n = (size_t)TOK * IDIM;
            silu_mul_split_kernel<<<(unsigned)((n + 255) / 256), 256>>>(mg, mu, ah, al, n);
        }
        launch_gemm3(ah, al, wth + base + OWD, wtl + base + OWD, h, 0, 0, TOK, H, IDIM, 1);
    }

    // ---- Final norm + LM head ----
    rmsnorm_split_kernel<<<TOK, 256>>>(h, norm_w, ah, al, H);
    launch_gemm3(ah, al, wth + OLM, wtl + OLM, out, 0, 0, TOK, VOC, H, 0);
}

// round 15
// speedup vs baseline: 1.2074x; 1.0798x over previous
#include <cuda_runtime.h>
#include <cuda_bf16.h>
#include <math.h>
#include <stdint.h>

// ---------------- Model constants ----------------
#define LNUM 8
#define H    1024
#define NH   16
#define NKV  8
#define HD   128
#define IDIM 3072
#define VOC  32000
#define BATCH 2
#define SEQ  1024
#define TOK  (BATCH*SEQ)          // 2048
#define QD   (NH*HD)              // 2048
#define KVD  (NKV*HD)             // 1024
#define EPS  1e-6f
#define ATT_SCALE 0.08838834764831845f

// Per-layer transposed-weight offsets (bf16 hi/lo arrays, [N][K] layout)
// QKV contiguous: rows 0-2047 = Q, 2048-3071 = K, 3072-4095 = V
#define OWQKV 0
#define OWO   (OWQKV + (size_t)4096*H)
#define OWGU  (OWO + (size_t)H*QD)
#define OWD   (OWGU + (size_t)2*IDIM*H)
#define PLSZ  (OWD + (size_t)H*IDIM)
#define OLM   ((size_t)LNUM * PLSZ)
#define WT_TOTAL (OLM + (size_t)VOC*H)

// ---------------- Scratch (device globals; no allocation allowed) ----------------
__device__ float g_h  [(size_t)TOK * H];
__device__ float g_qk [(size_t)TOK * 3072];
__device__ float g_gu [(size_t)TOK * 6144];
__device__ float g_cos[(size_t)SEQ * 64];
__device__ float g_sin[(size_t)SEQ * 64];
__device__ __nv_bfloat16 g_wT_hi[WT_TOTAL];
__device__ __nv_bfloat16 g_wT_lo[WT_TOTAL];
__device__ __nv_bfloat16 g_a_hi[(size_t)TOK * IDIM];
__device__ __nv_bfloat16 g_a_lo[(size_t)TOK * IDIM];
__device__ __nv_bfloat16 g_qh[(size_t)TOK * QD];
__device__ __nv_bfloat16 g_ql[(size_t)TOK * QD];
__device__ __nv_bfloat16 g_kh[(size_t)TOK * KVD];
__device__ __nv_bfloat16 g_kl[(size_t)TOK * KVD];
__device__ __nv_bfloat16 g_vth[(size_t)TOK * KVD];   // [b][kvh][dim][seq]
__device__ __nv_bfloat16 g_vtl[(size_t)TOK * KVD];

// ---------------- PTX helpers ----------------
__device__ __forceinline__ uint32_t smem_to_u32(const void* p) {
    uint32_t a;
    asm("{ .reg .u64 t; cvta.to.shared.u64 t, %1; cvt.u32.u64 %0, t; }" : "=r"(a) : "l"(p));
    return a;
}
__device__ __forceinline__ void cp16(uint32_t s, const void* g) {
    asm volatile("cp.async.cg.shared.global [%0], [%1], 16;" :: "r"(s), "l"(g));
}
__device__ __forceinline__ void ldsm4(uint32_t* r, uint32_t addr) {
    asm volatile("ldmatrix.sync.aligned.m8n8.x4.shared.b16 {%0,%1,%2,%3}, [%4];"
                 : "=r"(r[0]), "=r"(r[1]), "=r"(r[2]), "=r"(r[3]) : "r"(addr));
}
__device__ __forceinline__ void mma_bf16(float* c, const uint32_t* a, uint32_t b0, uint32_t b1) {
    asm volatile("mma.sync.aligned.m16n8k16.row.col.f32.bf16.bf16.f32 "
                 "{%0,%1,%2,%3}, {%4,%5,%6,%7}, {%8,%9}, {%0,%1,%2,%3};"
                 : "+f"(c[0]), "+f"(c[1]), "+f"(c[2]), "+f"(c[3])
                 : "r"(a[0]), "r"(a[1]), "r"(a[2]), "r"(a[3]), "r"(b0), "r"(b1));
}
#define SWZ(off) ((off) ^ (((off) >> 3) & 0x70))

__device__ __forceinline__ uint32_t pack_bf16(float a, float b) {
    __nv_bfloat162 h;
    h.x = __float2bfloat16(a);
    h.y = __float2bfloat16(b);
    return *(uint32_t*)&h;
}

// ---------------- Fused weight transpose + hi/lo bf16 split ----------------
// One launch converts ALL weight matrices: W[KxN] fp32 -> T[N][K] bf16 hi/lo.
#define NSEG 57
struct ConvSeg { const float* src; size_t dstOff; int K; int N; int blockBase; };
struct ConvTable { ConvSeg s[NSEG]; int total; };

__global__ __launch_bounds__(256) void convT_all_kernel(ConvTable tab,
                                                        __nv_bfloat16* __restrict__ Th,
                                                        __nv_bfloat16* __restrict__ Tl) {
    __shared__ float sm[64][65];
    int bid = blockIdx.x;
    // find segment (linear scan; NSEG small)
    int si = 0;
#pragma unroll 1
    for (int i = 1; i < NSEG; i++)
        if (bid >= tab.s[i].blockBase) si = i;
    const float* W = tab.s[si].src;
    int K = tab.s[si].K, N = tab.s[si].N;
    size_t doff = tab.s[si].dstOff;
    int local = bid - tab.s[si].blockBase;
    int nb = N >> 6;
    int n0 = (local % nb) << 6;
    int k0 = (local / nb) << 6;

    int t = threadIdx.x;
    int rr = t >> 4, cc = (t & 15) * 4;
#pragma unroll
    for (int it = 0; it < 4; it++) {
        int kr = rr + it * 16;
        float4 v = *(const float4*)&W[(size_t)(k0 + kr) * N + n0 + cc];
        sm[kr][cc + 0] = v.x;  sm[kr][cc + 1] = v.y;
        sm[kr][cc + 2] = v.z;  sm[kr][cc + 3] = v.w;
    }
    __syncthreads();
#pragma unroll
    for (int it = 0; it < 4; it++) {
        int nr = rr + it * 16;
        float v0 = sm[cc + 0][nr], v1 = sm[cc + 1][nr];
        float v2 = sm[cc + 2][nr], v3 = sm[cc + 3][nr];
        __nv_bfloat16 h0 = __float2bfloat16(v0), h1 = __float2bfloat16(v1);
        __nv_bfloat16 h2 = __float2bfloat16(v2), h3 = __float2bfloat16(v3);
        uint32_t hp0 = pack_bf16(v0, v1), hp1 = pack_bf16(v2, v3);
        uint32_t lp0 = pack_bf16(v0 - __bfloat162float(h0), v1 - __bfloat162float(h1));
        uint32_t lp1 = pack_bf16(v2 - __bfloat162float(h2), v3 - __bfloat162float(h3));
        size_t o = doff + (size_t)(n0 + nr) * K + k0 + cc;
        *(uint2*)&Th[o] = make_uint2(hp0, hp1);
        *(uint2*)&Tl[o] = make_uint2(lp0, lp1);
    }
}

// ---------------- bf16x3 GEMM via mma.sync: C = A @ B^T (B stored [N][K]) -----------
// 128x64 CTA tile, 8 warps (4x2), warp tile 32x32, BK=64, 2-stage cp.async,
// 1 barrier/iter, 96KB smem -> 2 CTAs/SM.
// mode 0: C = acc; mode 1: C += acc;
// mode 3 (QKV): block cols < 3072 -> C (ldc=3072); cols >= 3072 -> V-transposed hi/lo.
#define STG 49152
#define GSM_TOTAL (2 * STG)
__global__ __launch_bounds__(256, 2) void gemm_mma_kernel(
    const __nv_bfloat16* __restrict__ Ah, const __nv_bfloat16* __restrict__ Al,
    const __nv_bfloat16* __restrict__ Bh, const __nv_bfloat16* __restrict__ Bl,
    float* __restrict__ C, __nv_bfloat16* __restrict__ Oh, __nv_bfloat16* __restrict__ Ol,
    int M, int N, int K, int mode) {
    extern __shared__ char smem[];
    uint32_t sb = smem_to_u32(smem);
    int tid = threadIdx.x, lane = tid & 31, wid = tid >> 5;
    int brow = blockIdx.y * 128, bcol = blockIdx.x * 64;
    int wm = wid & 3, wn = wid >> 2;

    float acc[2][4][4] = {};
    int T = K >> 6;

    auto issue_loads = [&](int t) {
        uint32_t st = sb + (uint32_t)(t & 1) * STG;
        int k0 = t << 6;
#pragma unroll
        for (int i = 0; i < 4; i++) {
            int idx = tid + i * 256;
            int r = idx >> 3, g = idx & 7;
            uint32_t off = SWZ((uint32_t)(r * 128 + g * 16));
            size_t ga = (size_t)(brow + r) * K + k0 + g * 8;
            cp16(st + off,         Ah + ga);
            cp16(st + 16384 + off, Al + ga);
        }
#pragma unroll
        for (int i = 0; i < 2; i++) {
            int idx = tid + i * 256;
            int r = idx >> 3, g = idx & 7;
            uint32_t off = SWZ((uint32_t)(r * 128 + g * 16));
            size_t gb = (size_t)(bcol + r) * K + k0 + g * 8;
            cp16(st + 32768 + off, Bh + gb);
            cp16(st + 40960 + off, Bl + gb);
        }
        asm volatile("cp.async.commit_group;");
    };

    issue_loads(0);

    uint32_t a_roff = (uint32_t)(wm * 32 + (lane & 15));
    uint32_t a_koff = (uint32_t)((lane >> 4) * 8);
    uint32_t b_noff = (uint32_t)(wn * 32 + ((lane >> 4) * 8) + (lane & 7));
    uint32_t b_koff = (uint32_t)(((lane >> 3) & 1) * 8);

    for (int t = 0; t < T; t++) {
        asm volatile("cp.async.wait_group 0;");
        __syncthreads();
        if (t + 1 < T) issue_loads(t + 1);
        uint32_t st = sb + (uint32_t)(t & 1) * STG;
#pragma unroll
        for (int kk = 0; kk < 4; kk++) {
            uint32_t ah_[2][4], al_[2][4];
#pragma unroll
            for (int mi = 0; mi < 2; mi++) {
                uint32_t off = SWZ((a_roff + mi * 16) * 128 + (kk * 16 + a_koff) * 2);
                ldsm4(ah_[mi], st + off);
                ldsm4(al_[mi], st + 16384 + off);
            }
            uint32_t bh_[2][4], bl_[2][4];
#pragma unroll
            for (int p = 0; p < 2; p++) {
                uint32_t off = SWZ((b_noff + p * 16) * 128 + (kk * 16 + b_koff) * 2);
                ldsm4(bh_[p], st + 32768 + off);
                ldsm4(bl_[p], st + 40960 + off);
            }
#pragma unroll
            for (int mi = 0; mi < 2; mi++)
#pragma unroll
                for (int ni = 0; ni < 4; ni++) {
                    int p = ni >> 1, q2 = (ni & 1) * 2;
                    mma_bf16(acc[mi][ni], ah_[mi], bh_[p][q2], bh_[p][q2 + 1]);
                    mma_bf16(acc[mi][ni], ah_[mi], bl_[p][q2], bl_[p][q2 + 1]);
                    mma_bf16(acc[mi][ni], al_[mi], bh_[p][q2], bh_[p][q2 + 1]);
                }
        }
    }

    int vblock = (mode == 3) && (bcol >= 3072);
    int ldc = (mode == 3) ? 3072 : N;

#pragma unroll
    for (int mi = 0; mi < 2; mi++)
#pragma unroll
        for (int ni = 0; ni < 4; ni++) {
            int r0 = brow + wm * 32 + mi * 16 + (lane >> 2);
            int c0 = bcol + wn * 32 + ni * 8 + 2 * (lane & 3);
            float* a4 = acc[mi][ni];
            if (vblock) {
#pragma unroll
                for (int e = 0; e < 4; e++) {
                    int r = r0 + (e >> 1) * 8;
                    int c = c0 + (e & 1) - 3072;
                    int b = r >> 10, seq = r & 1023;
                    int kvh = c >> 7, hd = c & 127;
                    size_t idx = ((size_t)((b * NKV + kvh) * HD + hd)) * SEQ + seq;
                    float v = a4[e];
                    __nv_bfloat16 hi = __float2bfloat16(v);
                    Oh[idx] = hi;
                    Ol[idx] = __float2bfloat16(v - __bfloat162float(hi));
                }
            } else {
                float2* p0 = (float2*)(C + (size_t)r0 * ldc + c0);
                float2* p1 = (float2*)(C + (size_t)(r0 + 8) * ldc + c0);
                if (mode == 1) {
                    float2 v0 = *p0, v1 = *p1;
                    v0.x += a4[0]; v0.y += a4[1];
                    v1.x += a4[2]; v1.y += a4[3];
                    *p0 = v0; *p1 = v1;
                } else {
                    *p0 = make_float2(a4[0], a4[1]);
                    *p1 = make_float2(a4[2], a4[3]);
                }
            }
        }
}

// ---------------- Tensor-core flash attention (known good) ------------------
// Block: (b, h, 64-query tile). 4 warps, warp owns 16 q rows. K-tiles of 64 keys.
// smem: QH 0 | QL 16K | KH 32K | KL 48K | VH 64K | VL 80K  (96KB total)
#define ASM_BYTES 98304
__global__ __launch_bounds__(128, 2) void flash_attn_tc_kernel(
    const __nv_bfloat16* __restrict__ qh, const __nv_bfloat16* __restrict__ ql,
    const __nv_bfloat16* __restrict__ kh, const __nv_bfloat16* __restrict__ kl,
    const __nv_bfloat16* __restrict__ vth, const __nv_bfloat16* __restrict__ vtl,
    __nv_bfloat16* __restrict__ oh, __nv_bfloat16* __restrict__ ol) {
    extern __shared__ char smem[];
    uint32_t sb = smem_to_u32(smem);
    int tid = threadIdx.x, lane = tid & 31, w = tid >> 5;
    int gid = blockIdx.x;
    int qt = gid & 15, hh = (gid >> 4) & 15, b = gid >> 8;
    int t0 = qt * 64;
    int kvh = hh >> 1;

    for (int i = tid; i < 1024; i += 128) {
        int c = i >> 9, r = (i >> 3) & 63, g = i & 7;
        uint32_t off = c * 8192 + SWZ((uint32_t)(r * 128 + g * 16));
        size_t gq = ((size_t)(b * SEQ + t0 + r) * NH + hh) * HD + c * 64 + g * 8;
        cp16(sb + off,         qh + gq);
        cp16(sb + 16384 + off, ql + gq);
    }
    asm volatile("cp.async.commit_group;");
    asm volatile("cp.async.wait_group 0;");
    __syncthreads();

    uint32_t qah[2][4][4], qal[2][4][4];
#pragma unroll
    for (int c = 0; c < 2; c++)
#pragma unroll
        for (int kk = 0; kk < 4; kk++) {
            uint32_t off = c * 8192 +
                SWZ((uint32_t)((w * 16 + (lane & 15)) * 128 + (kk * 16 + (lane >> 4) * 8) * 2));
            ldsm4(qah[c][kk], sb + off);
            ldsm4(qal[c][kk], sb + 16384 + off);
        }

    float cacc[16][4] = {};
    float m0 = -1e30f, m1 = -1e30f, l0 = 0.f, l1 = 0.f;
    int r0g = t0 + w * 16 + (lane >> 2);
    int r1g = r0g + 8;

    for (int j0 = 0; j0 <= t0; j0 += 64) {
        for (int i = tid; i < 1024; i += 128) {
            int c = i >> 9, r = (i >> 3) & 63, g = i & 7;
            uint32_t koff = c * 8192 + SWZ((uint32_t)(r * 128 + g * 16));
            size_t gk = ((size_t)(b * SEQ + j0 + r) * NKV + kvh) * HD + c * 64 + g * 8;
            cp16(sb + 32768 + koff, kh + gk);
            cp16(sb + 49152 + koff, kl + gk);
            int dim = i >> 3, g2 = i & 7;
            uint32_t voff = SWZ((uint32_t)(dim * 128 + g2 * 16));
            size_t gv = ((size_t)((b * NKV + kvh) * HD + dim)) * SEQ + j0 + g2 * 8;
            cp16(sb + 65536 + voff, vth + gv);
            cp16(sb + 81920 + voff, vtl + gv);
        }
        asm volatile("cp.async.commit_group;");
        asm volatile("cp.async.wait_group 0;");
        __syncthreads();

        float sacc[8][4] = {};
#pragma unroll
        for (int c = 0; c < 2; c++)
#pragma unroll
            for (int kk = 0; kk < 4; kk++) {
#pragma unroll
                for (int p = 0; p < 4; p++) {
                    uint32_t off = c * 8192 +
                        SWZ((uint32_t)((p * 16 + (lane >> 4) * 8 + (lane & 7)) * 128 +
                                       (kk * 16 + ((lane >> 3) & 1) * 8) * 2));
                    uint32_t bh4[4], bl4[4];
                    ldsm4(bh4, sb + 32768 + off);
                    ldsm4(bl4, sb + 49152 + off);
                    mma_bf16(sacc[2 * p],     qah[c][kk], bh4[0], bh4[1]);
                    mma_bf16(sacc[2 * p],     qah[c][kk], bl4[0], bl4[1]);
                    mma_bf16(sacc[2 * p],     qal[c][kk], bh4[0], bh4[1]);
                    mma_bf16(sacc[2 * p + 1], qah[c][kk], bh4[2], bh4[3]);
                    mma_bf16(sacc[2 * p + 1], qah[c][kk], bl4[2], bl4[3]);
                    mma_bf16(sacc[2 * p + 1], qal[c][kk], bh4[2], bh4[3]);
                }
            }

        if (j0 == t0) {
#pragma unroll
            for (int ni = 0; ni < 8; ni++) {
                int colb = j0 + ni * 8 + 2 * (lane & 3);
                if (colb     > r0g) sacc[ni][0] = -1e30f;
                if (colb + 1 > r0g) sacc[ni][1] = -1e30f;
                if (colb     > r1g) sacc[ni][2] = -1e30f;
                if (colb + 1 > r1g) sacc[ni][3] = -1e30f;
            }
        }

        float rmax0 = -1e30f, rmax1 = -1e30f;
#pragma unroll
        for (int ni = 0; ni < 8; ni++) {
            rmax0 = fmaxf(rmax0, fmaxf(sacc[ni][0], sacc[ni][1]));
            rmax1 = fmaxf(rmax1, fmaxf(sacc[ni][2], sacc[ni][3]));
        }
        rmax0 = fmaxf(rmax0, __shfl_xor_sync(0xffffffffu, rmax0, 1));
        rmax0 = fmaxf(rmax0, __shfl_xor_sync(0xffffffffu, rmax0, 2));
        rmax1 = fmaxf(rmax1, __shfl_xor_sync(0xffffffffu, rmax1, 1));
        rmax1 = fmaxf(rmax1, __shfl_xor_sync(0xffffffffu, rmax1, 2));
        float mn0 = fmaxf(m0, rmax0), mn1 = fmaxf(m1, rmax1);
        float corr0 = __expf(m0 - mn0), corr1 = __expf(m1 - mn1);
        float rs0 = 0.f, rs1 = 0.f;
#pragma unroll
        for (int ni = 0; ni < 8; ni++) {
            sacc[ni][0] = __expf(sacc[ni][0] - mn0);
            sacc[ni][1] = __expf(sacc[ni][1] - mn0);
            sacc[ni][2] = __expf(sacc[ni][2] - mn1);
            sacc[ni][3] = __expf(sacc[ni][3] - mn1);
            rs0 += sacc[ni][0] + sacc[ni][1];
            rs1 += sacc[ni][2] + sacc[ni][3];
        }
        rs0 += __shfl_xor_sync(0xffffffffu, rs0, 1);
        rs0 += __shfl_xor_sync(0xffffffffu, rs0, 2);
        rs1 += __shfl_xor_sync(0xffffffffu, rs1, 1);
        rs1 += __shfl_xor_sync(0xffffffffu, rs1, 2);
        l0 = l0 * corr0 + rs0;  m0 = mn0;
        l1 = l1 * corr1 + rs1;  m1 = mn1;
#pragma unroll
        for (int n = 0; n < 16; n++) {
            cacc[n][0] *= corr0; cacc[n][1] *= corr0;
            cacc[n][2] *= corr1; cacc[n][3] *= corr1;
        }

#pragma unroll
        for (int kk = 0; kk < 4; kk++) {
            uint32_t pah[4], pal[4];
            float* s0 = sacc[2 * kk];
            float* s1 = sacc[2 * kk + 1];
            pah[0] = pack_bf16(s0[0], s0[1]);
            pah[1] = pack_bf16(s0[2], s0[3]);
            pah[2] = pack_bf16(s1[0], s1[1]);
            pah[3] = pack_bf16(s1[2], s1[3]);
            {
                __nv_bfloat162* hx;
                hx = (__nv_bfloat162*)&pah[0];
                pal[0] = pack_bf16(s0[0] - __bfloat162float(hx->x), s0[1] - __bfloat162float(hx->y));
                hx = (__nv_bfloat162*)&pah[1];
                pal[1] = pack_bf16(s0[2] - __bfloat162float(hx->x), s0[3] - __bfloat162float(hx->y));
                hx = (__nv_bfloat162*)&pah[2];
                pal[2] = pack_bf16(s1[0] - __bfloat162float(hx->x), s1[1] - __bfloat162float(hx->y));
                hx = (__nv_bfloat162*)&pah[3];
                pal[3] = pack_bf16(s1[2] - __bfloat162float(hx->x), s1[3] - __bfloat162float(hx->y));
            }
#pragma unroll
            for (int p = 0; p < 8; p++) {
                uint32_t off = SWZ((uint32_t)((p * 16 + (lane >> 4) * 8 + (lane & 7)) * 128 +
                                              (kk * 16 + ((lane >> 3) & 1) * 8) * 2));
                uint32_t vh4[4], vl4[4];
                ldsm4(vh4, sb + 65536 + off);
                ldsm4(vl4, sb + 81920 + off);
                mma_bf16(cacc[2 * p],     pah, vh4[0], vh4[1]);
                mma_bf16(cacc[2 * p],     pah, vl4[0], vl4[1]);
                mma_bf16(cacc[2 * p],     pal, vh4[0], vh4[1]);
                mma_bf16(cacc[2 * p + 1], pah, vh4[2], vh4[3]);
                mma_bf16(cacc[2 * p + 1], pah, vl4[2], vl4[3]);
                mma_bf16(cacc[2 * p + 1], pal, vh4[2], vh4[3]);
            }
        }
        __syncthreads();
    }

    float inv0 = 1.f / l0, inv1 = 1.f / l1;
    size_t tok0 = (size_t)(b * SEQ) + t0 + w * 16 + (lane >> 2);
    size_t tok1 = tok0 + 8;
#pragma unroll
    for (int n = 0; n < 16; n++) {
        int col = hh * HD + n * 8 + 2 * (lane & 3);
        float v0 = cacc[n][0] * inv0, v1 = cacc[n][1] * inv0;
        float v2 = cacc[n][2] * inv1, v3 = cacc[n][3] * inv1;
        uint32_t h0 = pack_bf16(v0, v1);
        uint32_t h1 = pack_bf16(v2, v3);
        __nv_bfloat162* hp;
        hp = (__nv_bfloat162*)&h0;
        uint32_t lo0 = pack_bf16(v0 - __bfloat162float(hp->x), v1 - __bfloat162float(hp->y));
        hp = (__nv_bfloat162*)&h1;
        uint32_t lo1 = pack_bf16(v2 - __bfloat162float(hp->x), v3 - __bfloat162float(hp->y));
        *(uint32_t*)&oh[tok0 * QD + col] = h0;
        *(uint32_t*)&ol[tok0 * QD + col] = lo0;
        *(uint32_t*)&oh[tok1 * QD + col] = h1;
        *(uint32_t*)&ol[tok1 * QD + col] = lo1;
    }
}

// ---------------- RoPE tables ----------------
__global__ void rope_table_kernel(float* __restrict__ cost, float* __restrict__ sint) {
    int pos = blockIdx.x;
    int i   = threadIdx.x;
    float invf = (float)pow(1000000.0, -(double)i / 64.0);
    float angf = (float)pos * invf;
    double ang = (double)angf;
    cost[pos * 64 + i] = (float)cos(ang);
    sint[pos * 64 + i] = (float)sin(ang);
}

// ---------------- Embedding gather ----------------
__global__ void embed_kernel(const int* __restrict__ ids,
                             const float* __restrict__ emb,
                             float* __restrict__ out) {
    int t = blockIdx.x;
    int id = ids[t];
    const float4* src = (const float4*)(emb + (size_t)id * H);
    float4* dst = (float4*)(out + (size_t)t * H);
    for (int i = threadIdx.x; i < H / 4; i += blockDim.x) dst[i] = src[i];
}

// ---------------- Row RMSNorm with fused bf16 hi/lo split ----------------
__global__ void rmsnorm_split_kernel(const float* __restrict__ in,
                                     const float* __restrict__ w,
                                     __nv_bfloat16* __restrict__ oh,
                                     __nv_bfloat16* __restrict__ ol, int W) {
    __shared__ float red[256];
    int row = blockIdx.x;
    const float* x = in + (size_t)row * W;
    float s = 0.f;
    for (int i = threadIdx.x; i < W; i += 256) { float v = x[i]; s += v * v; }
    red[threadIdx.x] = s;
    __syncthreads();
    for (int st = 128; st > 0; st >>= 1) {
        if (threadIdx.x < st) red[threadIdx.x] += red[threadIdx.x + st];
        __syncthreads();
    }
    float rms = rsqrtf(red[0] / (float)W + EPS);
    for (int i = threadIdx.x; i < W; i += 256) {
        float v = x[i] * rms * w[i];
        __nv_bfloat16 hi = __float2bfloat16(v);
        size_t o = (size_t)row * W + i;
        oh[o] = hi;
        ol[o] = __float2bfloat16(v - __bfloat162float(hi));
    }
}

// ---------------- Per-head RMSNorm + RoPE + bf16 hi/lo split (strided input) --------
__global__ void qk_norm_rope_split_kernel(const float* __restrict__ x,
                                          int xstride, int colbase,
                                          const float* __restrict__ w,
                                          const float* __restrict__ cost,
                                          const float* __restrict__ sint,
                                          __nv_bfloat16* __restrict__ oh,
                                          __nv_bfloat16* __restrict__ ol,
                                          int nheads, float scale) {
    __shared__ float sh[HD];
    __shared__ float red[HD];
    int t  = blockIdx.x / nheads;
    int hh = blockIdx.x % nheads;
    int pos = t % SEQ;
    const float* p = x + (size_t)t * xstride + colbase + hh * HD;
    int d = threadIdx.x;
    float v = p[d];
    red[d] = v * v;
    __syncthreads();
    for (int st = 64; st > 0; st >>= 1) {
        if (d < st) red[d] += red[d + st];
        __syncthreads();
    }
    float rms = rsqrtf(red[0] / (float)HD + EPS);
    float xn = v * rms * w[d];
    sh[d] = xn;
    __syncthreads();
    int fi = d & 63;
    float c = cost[pos * 64 + fi];
    float s = sint[pos * 64 + fi];
    float other = (d < 64) ? -sh[d + 64] : sh[d - 64];
    float val = (xn * c + other * s) * scale;
    __nv_bfloat16 hi = __float2bfloat16(val);
    size_t o = ((size_t)t * nheads + hh) * HD + d;
    oh[o] = hi;
    ol[o] = __float2bfloat16(val - __bfloat162float(hi));
}

// ---------------- SiLU(g) * u from fused GU buffer, with bf16 hi/lo split ------------
__global__ void silu_mul_split_kernel(const float* __restrict__ gu,
                                      __nv_bfloat16* __restrict__ oh,
                                      __nv_bfloat16* __restrict__ ol, size_t n) {
    size_t i = (size_t)blockIdx.x * blockDim.x + threadIdx.x;
    if (i < n) {
        size_t t = i / IDIM, j = i % IDIM;
        const float* row = gu + t * (2 * IDIM);
        float x = row[j];
        float u = row[IDIM + j];
        float val = (x / (1.f + __expf(-x))) * u;
        __nv_bfloat16 hi = __float2bfloat16(val);
        oh[i] = hi;
        ol[i] = __float2bfloat16(val - __bfloat162float(hi));
    }
}

// ---------------- Host orchestration ----------------
static void launch_gemm3(const __nv_bfloat16* Ah, const __nv_bfloat16* Al,
                         const __nv_bfloat16* Bh, const __nv_bfloat16* Bl,
                         float* C, __nv_bfloat16* Oh, __nv_bfloat16* Ol,
                         int M, int N, int K, int mode) {
    dim3 grid(N / 64, M / 128);
    gemm_mma_kernel<<<grid, 256, GSM_TOTAL>>>(Ah, Al, Bh, Bl, C, Oh, Ol, M, N, K, mode);
}

extern "C" void kernel_launch(void* const* d_in, const int* in_sizes, int n_in,
                              void* d_out, int out_size) {
    const int*   input_ids = (const int*)  d_in[0];
    const float* embed     = (const float*)d_in[1];
    const float* Wq        = (const float*)d_in[2];
    const float* Wk        = (const float*)d_in[3];
    const float* Wv        = (const float*)d_in[4];
    const float* Wo        = (const float*)d_in[5];
    const float* qn        = (const float*)d_in[6];
    const float* kn        = (const float*)d_in[7];
    const float* ln1       = (const float*)d_in[8];
    const float* ln2       = (const float*)d_in[9];
    const float* Wg        = (const float*)d_in[10];
    const float* Wu        = (const float*)d_in[11];
    const float* Wd        = (const float*)d_in[12];
    const float* norm_w    = (const float*)d_in[13];
    const float* lm_head   = (const float*)d_in[14];
    float* out = (float*)d_out;

    float *h, *qk, *gu, *cost, *sint;
    __nv_bfloat16 *wth, *wtl, *ah, *al, *qh, *ql, *kh, *kl, *vth, *vtl;
    cudaGetSymbolAddress((void**)&h,    g_h);
    cudaGetSymbolAddress((void**)&qk,   g_qk);
    cudaGetSymbolAddress((void**)&gu,   g_gu);
    cudaGetSymbolAddress((void**)&cost, g_cos);
    cudaGetSymbolAddress((void**)&sint, g_sin);
    cudaGetSymbolAddress((void**)&wth,  g_wT_hi);
    cudaGetSymbolAddress((void**)&wtl,  g_wT_lo);
    cudaGetSymbolAddress((void**)&ah,   g_a_hi);
    cudaGetSymbolAddress((void**)&al,   g_a_lo);
    cudaGetSymbolAddress((void**)&qh,   g_qh);
    cudaGetSymbolAddress((void**)&ql,   g_ql);
    cudaGetSymbolAddress((void**)&kh,   g_kh);
    cudaGetSymbolAddress((void**)&kl,   g_kl);
    cudaGetSymbolAddress((void**)&vth,  g_vth);
    cudaGetSymbolAddress((void**)&vtl,  g_vtl);

    cudaFuncSetAttribute(gemm_mma_kernel,
                         cudaFuncAttributeMaxDynamicSharedMemorySize, GSM_TOTAL);
    cudaFuncSetAttribute(flash_attn_tc_kernel,
                         cudaFuncAttributeMaxDynamicSharedMemorySize, ASM_BYTES);

    // ---- Build conversion table: 57 segments (7 per layer + LM head) ----
    ConvTable tab;
    int nseg = 0, blk = 0;
    auto add = [&](const float* src, size_t dstOff, int K, int N) {
        tab.s[nseg].src = src;
        tab.s[nseg].dstOff = dstOff;
        tab.s[nseg].K = K;
        tab.s[nseg].N = N;
        tab.s[nseg].blockBase = blk;
        blk += (N / 64) * (K / 64);
        nseg++;
    };
    for (int l = 0; l < LNUM; l++) {
        size_t base = (size_t)l * PLSZ;
        add(Wq + (size_t)l * H * QD,   base + OWQKV,                  H,    QD);
        add(Wk + (size_t)l * H * KVD,  base + OWQKV + (size_t)QD * H, H,    KVD);
        add(Wv + (size_t)l * H * KVD,  base + OWQKV + (size_t)(QD + KVD) * H, H, KVD);
        add(Wo + (size_t)l * QD * H,   base + OWO,                    QD,   H);
        add(Wg + (size_t)l * H * IDIM, base + OWGU,                   H,    IDIM);
        add(Wu + (size_t)l * H * IDIM, base + OWGU + (size_t)IDIM * H, H,   IDIM);
        add(Wd + (size_t)l * IDIM * H, base + OWD,                    IDIM, H);
    }
    add(lm_head, OLM, H, VOC);
    tab.total = blk;

    // Launch #1: fused weight conversion (all matrices)
    convT_all_kernel<<<blk, 256>>>(tab, wth, wtl);
    // Launch #2: embedding
    embed_kernel<<<TOK, 256>>>(input_ids, embed, h);

    for (int l = 0; l < LNUM; l++) {
        size_t base = (size_t)l * PLSZ;

        // ---- Attention block ----
        rmsnorm_split_kernel<<<TOK, 256>>>(h, ln1 + (size_t)l * H, ah, al, H);   // #3 (l=0)
        launch_gemm3(ah, al, wth + base + OWQKV, wtl + base + OWQKV,
                     qk, vth, vtl, TOK, 4096, H, 3);                             // #4 <- profiled
        if (l == 0) rope_table_kernel<<<SEQ, 64>>>(cost, sint);                  // #5
        qk_norm_rope_split_kernel<<<TOK * NH,  HD>>>(qk, 3072, 0,  qn + (size_t)l * HD,
                                                     cost, sint, qh, ql, NH,  ATT_SCALE);
        qk_norm_rope_split_kernel<<<TOK * NKV, HD>>>(qk, 3072, QD, kn + (size_t)l * HD,
                                                     cost, sint, kh, kl, NKV, 1.0f);
        flash_attn_tc_kernel<<<BATCH * NH * (SEQ / 64), 128, ASM_BYTES>>>(
            qh, ql, kh, kl, vth, vtl, ah, al);
        launch_gemm3(ah, al, wth + base + OWO, wtl + base + OWO, h, 0, 0, TOK, H, QD, 1);

        // ---- MLP block ----
        rmsnorm_split_kernel<<<TOK, 256>>>(h, ln2 + (size_t)l * H, ah, al, H);
        launch_gemm3(ah, al, wth + base + OWGU, wtl + base + OWGU, gu, 0, 0, TOK, 2 * IDIM, H, 0);
        {
            size_t n = (size_t)TOK * IDIM;
            silu_mul_split_kernel<<<(unsigned)((n + 255) / 256), 256>>>(gu, ah, al, n);
        }
        launch_gemm3(ah, al, wth + base + OWD, wtl + base + OWD, h, 0, 0, TOK, H, IDIM, 1);
    }

    // ---- Final norm + LM head ----
    rmsnorm_split_kernel<<<TOK, 256>>>(h, norm_w, ah, al, H);
    launch_gemm3(ah, al, wth + OLM, wtl + OLM, out, 0, 0, TOK, VOC, H, 0);
}